// round 1
// baseline (speedup 1.0000x reference)
#include <cuda_runtime.h>
#include <math.h>

// ---------------- problem constants ----------------
#define BQ   512
#define CC   256
#define HH   7
#define WWD  7
#define HWX  49            // 7*7
#define M1   (BQ*HWX)      // 25088
#define SS   20
#define HWS  256           // 16*16
#define MS   (SS*HWS)      // 5120
#define REP  1024
#define FIN  (CC*HWX)      // 12544
#define CCAT 768

// ---------------- scratch (static device globals; no allocation) ----------------
__device__ float g_qv[(size_t)M1*CC];
__device__ float g_qk[(size_t)M1*CC];
__device__ float g_sv[(size_t)MS*CC];
__device__ float g_sk[(size_t)MS*CC];
__device__ float g_gapin[SS*CC];
__device__ float g_gapval[SS*CC];
__device__ float g_gapkey[SS*CC];
__device__ float g_S[(size_t)M1*MS];          // 513.8 MB similarity
__device__ float g_attn[(size_t)M1*CC];
__device__ float g_attnchl[(size_t)M1*CC];
__device__ float g_catin[(size_t)BQ*CCAT*HWX];
__device__ float g_fuse_nhwc[(size_t)M1*CC];
__device__ float g_fuse[(size_t)BQ*FIN];
__device__ float g_hr[(size_t)BQ*REP];
__device__ float g_hc[(size_t)BQ*REP];

// ---------------- generic 64x64x16 SGEMM ----------------
// C(M,N) = A(M,K) @ op(B) ; TB ? B is (N,K) row-major : B is (K,N) row-major.
// Requires M%64==0, N%64==0, K%16==0 (true for every call site here).
template<bool TB, bool BIAS, bool RELU>
__global__ __launch_bounds__(256)
void gemm64(const float* __restrict__ A, const float* __restrict__ B,
            const float* __restrict__ bias, float* __restrict__ C,
            int M, int N, int K)
{
    __shared__ float As[16][64];
    __shared__ float Bs[16][64];
    const int m0 = blockIdx.y * 64;
    const int n0 = blockIdx.x * 64;
    const int tid = threadIdx.x;
    const int tx = tid & 15, ty = tid >> 4;

    float acc[4][4] = {};

    const int a_r  = tid >> 2;        // 0..63 (row within tile)
    const int a_k4 = (tid & 3) * 4;   // 0,4,8,12

    for (int k0 = 0; k0 < K; k0 += 16) {
        // A tile (transposed into smem)
        float4 av = *(const float4*)(A + (size_t)(m0 + a_r) * K + k0 + a_k4);
        As[a_k4+0][a_r] = av.x; As[a_k4+1][a_r] = av.y;
        As[a_k4+2][a_r] = av.z; As[a_k4+3][a_r] = av.w;
        // B tile
        if (TB) {
            float4 bv = *(const float4*)(B + (size_t)(n0 + a_r) * K + k0 + a_k4);
            Bs[a_k4+0][a_r] = bv.x; Bs[a_k4+1][a_r] = bv.y;
            Bs[a_k4+2][a_r] = bv.z; Bs[a_k4+3][a_r] = bv.w;
        } else {
            const int b_k  = tid >> 4;          // 0..15
            const int b_n4 = (tid & 15) * 4;    // 0..60
            float4 bv = *(const float4*)(B + (size_t)(k0 + b_k) * N + n0 + b_n4);
            *(float4*)&Bs[b_k][b_n4] = bv;
        }
        __syncthreads();
        #pragma unroll
        for (int kk = 0; kk < 16; kk++) {
            float4 a = *(const float4*)&As[kk][ty*4];
            float4 b = *(const float4*)&Bs[kk][tx*4];
            acc[0][0] += a.x*b.x; acc[0][1] += a.x*b.y; acc[0][2] += a.x*b.z; acc[0][3] += a.x*b.w;
            acc[1][0] += a.y*b.x; acc[1][1] += a.y*b.y; acc[1][2] += a.y*b.z; acc[1][3] += a.y*b.w;
            acc[2][0] += a.z*b.x; acc[2][1] += a.z*b.y; acc[2][2] += a.z*b.z; acc[2][3] += a.z*b.w;
            acc[3][0] += a.w*b.x; acc[3][1] += a.w*b.y; acc[3][2] += a.w*b.z; acc[3][3] += a.w*b.w;
        }
        __syncthreads();
    }

    #pragma unroll
    for (int i = 0; i < 4; i++) {
        const int row = m0 + ty*4 + i;
        float4 v = make_float4(acc[i][0], acc[i][1], acc[i][2], acc[i][3]);
        if (BIAS) {
            const float* bp = bias + n0 + tx*4;
            v.x += bp[0]; v.y += bp[1]; v.z += bp[2]; v.w += bp[3];
        }
        if (RELU) {
            v.x = fmaxf(v.x, 0.f); v.y = fmaxf(v.y, 0.f);
            v.z = fmaxf(v.z, 0.f); v.w = fmaxf(v.w, 0.f);
        }
        *(float4*)(C + (size_t)row * N + n0 + tx*4) = v;
    }
}

// ---------------- implicit-im2col 3x3 SAME conv as NT GEMM ----------------
// Out(M, 256) = im2col(X)(M, Cin*9) @ W(256, Cin*9)^T   (NHWC output)
// X is NCHW, W is OIHW (row-major (Cout, Cin*9)). M = Nimg*H*W, M%64==0.
template<bool RELU>
__global__ __launch_bounds__(256)
void conv3_igemm(const float* __restrict__ X, const float* __restrict__ Wt,
                 const float* __restrict__ bias, float* __restrict__ Out,
                 int M, int Cin, int HW, int Hdim, int Wdim)
{
    __shared__ float As[16][64];
    __shared__ float Bs[16][64];
    const int K = Cin * 9;
    const int m0 = blockIdx.y * 64;
    const int n0 = blockIdx.x * 64;     // cout tile
    const int tid = threadIdx.x;
    const int tx = tid & 15, ty = tid >> 4;

    // per-thread spatial decode for the A-gather (hoisted: fixed m per thread)
    const int l_m = tid & 63;
    const int l_k = tid >> 6;           // 0..3
    const int m   = m0 + l_m;
    const int nimg = m / HW;
    const int p    = m % HW;
    const int oh   = p / Wdim;
    const int ow   = p % Wdim;
    const float* xbase = X + (size_t)nimg * Cin * HW;

    const int b_n  = tid >> 2;          // 0..63
    const int b_k4 = (tid & 3) * 4;

    float acc[4][4] = {};

    for (int k0 = 0; k0 < K; k0 += 16) {
        #pragma unroll
        for (int r = 0; r < 4; r++) {
            const int k  = k0 + l_k + r*4;
            const int ci = k / 9;
            const int t  = k - ci*9;
            const int kh = t / 3;
            const int kw = t - kh*3;
            const int ih = oh + kh - 1;
            const int iw = ow + kw - 1;
            float v = 0.f;
            if (ih >= 0 && ih < Hdim && iw >= 0 && iw < Wdim)
                v = xbase[(size_t)ci * HW + ih * Wdim + iw];
            As[l_k + r*4][l_m] = v;
        }
        float4 bv = *(const float4*)(Wt + (size_t)(n0 + b_n) * K + k0 + b_k4);
        Bs[b_k4+0][b_n] = bv.x; Bs[b_k4+1][b_n] = bv.y;
        Bs[b_k4+2][b_n] = bv.z; Bs[b_k4+3][b_n] = bv.w;
        __syncthreads();
        #pragma unroll
        for (int kk = 0; kk < 16; kk++) {
            float4 a = *(const float4*)&As[kk][ty*4];
            float4 b = *(const float4*)&Bs[kk][tx*4];
            acc[0][0] += a.x*b.x; acc[0][1] += a.x*b.y; acc[0][2] += a.x*b.z; acc[0][3] += a.x*b.w;
            acc[1][0] += a.y*b.x; acc[1][1] += a.y*b.y; acc[1][2] += a.y*b.z; acc[1][3] += a.y*b.w;
            acc[2][0] += a.z*b.x; acc[2][1] += a.z*b.y; acc[2][2] += a.z*b.z; acc[2][3] += a.z*b.w;
            acc[3][0] += a.w*b.x; acc[3][1] += a.w*b.y; acc[3][2] += a.w*b.z; acc[3][3] += a.w*b.w;
        }
        __syncthreads();
    }

    #pragma unroll
    for (int i = 0; i < 4; i++) {
        const int row = m0 + ty*4 + i;
        float4 v = make_float4(acc[i][0], acc[i][1], acc[i][2], acc[i][3]);
        const float* bp = bias + n0 + tx*4;
        v.x += bp[0]; v.y += bp[1]; v.z += bp[2]; v.w += bp[3];
        if (RELU) {
            v.x = fmaxf(v.x, 0.f); v.y = fmaxf(v.y, 0.f);
            v.z = fmaxf(v.z, 0.f); v.w = fmaxf(v.w, 0.f);
        }
        *(float4*)(Out + (size_t)row * CC + n0 + tx*4) = v;
    }
}

// ---------------- sup spatial mean: (S,C,16,16) -> (S*C) ----------------
__global__ void gap_mean_kernel(const float* __restrict__ sup, float* __restrict__ out)
{
    const int gw = (blockIdx.x * blockDim.x + threadIdx.x) >> 5;   // global warp id
    const int lane = threadIdx.x & 31;
    if (gw >= SS*CC) return;
    const float* pch = sup + (size_t)gw * HWS;
    float s = 0.f;
    for (int i = lane; i < HWS; i += 32) s += pch[i];
    #pragma unroll
    for (int o = 16; o; o >>= 1) s += __shfl_xor_sync(0xffffffffu, s, o);
    if (lane == 0) out[gw] = s * (1.f / 256.f);
}

// ---------------- gap "convs" (center tap only) ----------------
// gapval[s][co] = sum_ci gapin[s][ci]*gk_w[co][ci][1][1] + gk_b[co]   (VALUE uses gk_*)
// gapkey[s][co] = sum_ci gapin[s][ci]*gv_w[co][ci][1][1] + gv_b[co]   (KEY   uses gv_*)
__global__ __launch_bounds__(256)
void gap_fc_kernel(const float* __restrict__ gapin,
                   const float* __restrict__ gkw, const float* __restrict__ gkb,
                   const float* __restrict__ gvw, const float* __restrict__ gvb,
                   float* __restrict__ gapval, float* __restrict__ gapkey)
{
    const int s = blockIdx.x;
    const int co = threadIdx.x;
    __shared__ float gin[CC];
    gin[co] = gapin[s*CC + co];
    __syncthreads();
    float a = gkb[co], b = gvb[co];
    for (int ci = 0; ci < CC; ci++) {
        const float g = gin[ci];
        a += g * gkw[(size_t)(co*CC + ci)*9 + 4];
        b += g * gvw[(size_t)(co*CC + ci)*9 + 4];
    }
    gapval[s*CC + co] = a;
    gapkey[s*CC + co] = b;
}

// ---------------- row softmax over N=5120 (in place) ----------------
__global__ __launch_bounds__(256)
void softmax_rows(float* __restrict__ S, int N)
{
    const int m = blockIdx.x;
    float* row = S + (size_t)m * N;
    __shared__ float sm[32];
    __shared__ float bcast;
    const int tid = threadIdx.x, lane = tid & 31, w = tid >> 5;

    float mx = -1e30f;
    for (int i = tid; i < N; i += 256) mx = fmaxf(mx, row[i]);
    #pragma unroll
    for (int o = 16; o; o >>= 1) mx = fmaxf(mx, __shfl_xor_sync(0xffffffffu, mx, o));
    if (lane == 0) sm[w] = mx;
    __syncthreads();
    if (tid < 32) {
        float v = (tid < 8) ? sm[tid] : -1e30f;
        #pragma unroll
        for (int o = 16; o; o >>= 1) v = fmaxf(v, __shfl_xor_sync(0xffffffffu, v, o));
        if (tid == 0) bcast = v;
    }
    __syncthreads();
    mx = bcast;
    __syncthreads();

    float sum = 0.f;
    for (int i = tid; i < N; i += 256) {
        float e = expf(row[i] - mx);
        row[i] = e;
        sum += e;
    }
    #pragma unroll
    for (int o = 16; o; o >>= 1) sum += __shfl_xor_sync(0xffffffffu, sum, o);
    if (lane == 0) sm[w] = sum;
    __syncthreads();
    if (tid < 32) {
        float v = (tid < 8) ? sm[tid] : 0.f;
        #pragma unroll
        for (int o = 16; o; o >>= 1) v += __shfl_xor_sync(0xffffffffu, v, o);
        if (tid == 0) bcast = v;
    }
    __syncthreads();
    const float inv = 1.f / bcast;
    for (int i = tid; i < N; i += 256) row[i] *= inv;
}

// ---------------- fused channel attention: softmax(qk@gapkey^T) @ gapval ----------------
__global__ __launch_bounds__(256)
void chl_attn_kernel(const float* __restrict__ qk, const float* __restrict__ gapkey,
                     const float* __restrict__ gapval, float* __restrict__ out)
{
    const int m = blockIdx.x;
    __shared__ float qrow[CC];
    __shared__ float pr[SS];
    const int tid = threadIdx.x;
    qrow[tid] = qk[(size_t)m*CC + tid];
    __syncthreads();
    if (tid < SS) {
        const float* krow = gapkey + tid*CC;
        float acc = 0.f;
        #pragma unroll 8
        for (int i = 0; i < CC; i++) acc += qrow[i] * krow[i];
        pr[tid] = acc;
    }
    __syncthreads();
    if (tid == 0) {
        float mx = -1e30f;
        #pragma unroll
        for (int s = 0; s < SS; s++) mx = fmaxf(mx, pr[s]);
        float sum = 0.f;
        #pragma unroll
        for (int s = 0; s < SS; s++) { float e = expf(pr[s] - mx); pr[s] = e; sum += e; }
        const float inv = 1.f / sum;
        #pragma unroll
        for (int s = 0; s < SS; s++) pr[s] *= inv;
    }
    __syncthreads();
    float acc = 0.f;
    #pragma unroll
    for (int s = 0; s < SS; s++) acc += pr[s] * gapval[s*CC + tid];
    out[(size_t)m*CC + tid] = acc;
}

// ---------------- NHWC(3 sources) -> NCHW pack (HW=49) ----------------
__global__ void nhwc_to_nchw3(float* __restrict__ dst,
                              const float* __restrict__ s0,
                              const float* __restrict__ s1,
                              const float* __restrict__ s2, int Ctot)
{
    __shared__ float tile[49][33];
    const int b = blockIdx.x, cg = blockIdx.y;
    const int tx = threadIdx.x, ty = threadIdx.y;   // (32, 8)
    const int c = cg*32 + tx;
    const float* src = (c < 256) ? s0 : ((c < 512) ? s1 : s2);
    const int cl = c & 255;
    for (int p = ty; p < 49; p += 8)
        tile[p][tx] = src[((size_t)b*49 + p)*256 + cl];
    __syncthreads();
    for (int cc = ty; cc < 32; cc += 8) {
        float* drow = dst + ((size_t)b*Ctot + cg*32 + cc) * 49;
        drow[tx] = tile[tx][cc];
        if (tx + 32 < 49) drow[tx + 32] = tile[tx + 32][cc];
    }
}

// ---------------- launch ----------------
extern "C" void kernel_launch(void* const* d_in, const int* in_sizes, int n_in,
                              void* d_out, int out_size)
{
    const float* x     = (const float*)d_in[0];
    const float* sup   = (const float*)d_in[1];
    const float* qv_w  = (const float*)d_in[2];
    const float* qv_b  = (const float*)d_in[3];
    const float* qk_w  = (const float*)d_in[4];
    const float* qk_b  = (const float*)d_in[5];
    const float* gk_w  = (const float*)d_in[6];
    const float* gk_b  = (const float*)d_in[7];
    const float* gv_w  = (const float*)d_in[8];
    const float* gv_b  = (const float*)d_in[9];
    const float* sv_w  = (const float*)d_in[10];
    const float* sv_b  = (const float*)d_in[11];
    const float* sk_w  = (const float*)d_in[12];
    const float* sk_b  = (const float*)d_in[13];
    const float* cat_w = (const float*)d_in[14];
    const float* cat_b = (const float*)d_in[15];
    const float* fc6c_w = (const float*)d_in[16];
    const float* fc6c_b = (const float*)d_in[17];
    const float* fc7c_w = (const float*)d_in[18];
    const float* fc7c_b = (const float*)d_in[19];
    const float* fc6r_w = (const float*)d_in[20];
    const float* fc6r_b = (const float*)d_in[21];
    const float* fc7r_w = (const float*)d_in[22];
    const float* fc7r_b = (const float*)d_in[23];
    float* out = (float*)d_out;

    float *p_qv, *p_qk, *p_sv, *p_sk, *p_gapin, *p_gapval, *p_gapkey;
    float *p_S, *p_attn, *p_attnchl, *p_catin, *p_fnhwc, *p_fuse, *p_hr, *p_hc;
    cudaGetSymbolAddress((void**)&p_qv, g_qv);
    cudaGetSymbolAddress((void**)&p_qk, g_qk);
    cudaGetSymbolAddress((void**)&p_sv, g_sv);
    cudaGetSymbolAddress((void**)&p_sk, g_sk);
    cudaGetSymbolAddress((void**)&p_gapin, g_gapin);
    cudaGetSymbolAddress((void**)&p_gapval, g_gapval);
    cudaGetSymbolAddress((void**)&p_gapkey, g_gapkey);
    cudaGetSymbolAddress((void**)&p_S, g_S);
    cudaGetSymbolAddress((void**)&p_attn, g_attn);
    cudaGetSymbolAddress((void**)&p_attnchl, g_attnchl);
    cudaGetSymbolAddress((void**)&p_catin, g_catin);
    cudaGetSymbolAddress((void**)&p_fnhwc, g_fuse_nhwc);
    cudaGetSymbolAddress((void**)&p_fuse, g_fuse);
    cudaGetSymbolAddress((void**)&p_hr, g_hr);
    cudaGetSymbolAddress((void**)&p_hc, g_hc);

    // 1) support GAP + center-tap gap convs
    gap_mean_kernel<<<(SS*CC*32 + 255)/256, 256>>>(sup, p_gapin);
    gap_fc_kernel<<<SS, 256>>>(p_gapin, gk_w, gk_b, gv_w, gv_b, p_gapval, p_gapkey);

    // 2) the four 3x3 convs (implicit GEMM, NHWC outputs)
    conv3_igemm<false><<<dim3(CC/64, M1/64), 256>>>(x,   qv_w, qv_b, p_qv, M1, CC, HWX, HH, WWD);
    conv3_igemm<false><<<dim3(CC/64, M1/64), 256>>>(x,   qk_w, qk_b, p_qk, M1, CC, HWX, HH, WWD);
    conv3_igemm<false><<<dim3(CC/64, MS/64), 256>>>(sup, sv_w, sv_b, p_sv, MS, CC, HWS, 16, 16);
    conv3_igemm<false><<<dim3(CC/64, MS/64), 256>>>(sup, sk_w, sk_b, p_sk, MS, CC, HWS, 16, 16);

    // 3) similarity = qk @ sk^T  (NT), softmax rows
    gemm64<true,false,false><<<dim3(MS/64, M1/64), 256>>>(p_qk, p_sk, nullptr, p_S, M1, MS, CC);
    softmax_rows<<<M1, 256>>>(p_S, MS);

    // 4) channel attention (fused logits+softmax+apply, N=20)
    chl_attn_kernel<<<M1, 256>>>(p_qk, p_gapkey, p_gapval, p_attnchl);

    // 5) attn = P @ V  (NN)
    gemm64<false,false,false><<<dim3(CC/64, M1/64), 256>>>(p_S, p_sv, nullptr, p_attn, M1, CC, MS);

    // 6) concat pack -> NCHW (B,768,7,7)
    nhwc_to_nchw3<<<dim3(BQ, CCAT/32), dim3(32,8)>>>(p_catin, p_qv, p_attn, p_attnchl, CCAT);

    // 7) cat conv (768->256) + ReLU, then pack NHWC -> (B, 12544) NCHW-flat
    conv3_igemm<true><<<dim3(CC/64, M1/64), 256>>>(p_catin, cat_w, cat_b, p_fnhwc, M1, CCAT, HWX, HH, WWD);
    nhwc_to_nchw3<<<dim3(BQ, CC/32), dim3(32,8)>>>(p_fuse, p_fnhwc, p_fnhwc, p_fnhwc, CC);

    // 8) FC heads: xc first, then xr (tuple order (xc, xr))
    gemm64<false,true,true><<<dim3(REP/64, BQ/64), 256>>>(p_fuse, fc6c_w, fc6c_b, p_hc, BQ, REP, FIN);
    gemm64<false,true,true><<<dim3(REP/64, BQ/64), 256>>>(p_hc, fc7c_w, fc7c_b, out, BQ, REP, REP);
    gemm64<false,true,true><<<dim3(REP/64, BQ/64), 256>>>(p_fuse, fc6r_w, fc6r_b, p_hr, BQ, REP, FIN);
    gemm64<false,true,true><<<dim3(REP/64, BQ/64), 256>>>(p_hr, fc7r_w, fc7r_b, out + (size_t)BQ*REP, BQ, REP, REP);
}

// round 3
// speedup vs baseline: 1.1567x; 1.1567x over previous
#include <cuda_runtime.h>
#include <cuda_bf16.h>
#include <math.h>
#include <stdint.h>

// ---------------- problem constants ----------------
#define BQ   512
#define CC   256
#define HH   7
#define WWD  7
#define HWX  49            // 7*7
#define M1   (BQ*HWX)      // 25088
#define SS   20
#define HWS  256           // 16*16
#define MS   (SS*HWS)      // 5120
#define REP  1024
#define FIN  (CC*HWX)      // 12544
#define CCAT 768

// ---------------- scratch (static device globals; no allocation) ----------------
__device__ float g_qv[(size_t)M1*CC];
__device__ float g_qk[(size_t)M1*CC];
__device__ float g_sv[(size_t)MS*CC];
__device__ float g_sk[(size_t)MS*CC];
__device__ float g_gapin[SS*CC];
__device__ float g_gapval[SS*CC];
__device__ float g_gapkey[SS*CC];
__device__ float g_S[(size_t)M1*MS];          // 513.8 MB similarity
__device__ float g_attn[(size_t)M1*CC];
__device__ float g_attnchl[(size_t)M1*CC];
__device__ float g_catin[(size_t)BQ*CCAT*HWX];
__device__ float g_fuse_nhwc[(size_t)M1*CC];
__device__ float g_fuse[(size_t)BQ*FIN];
__device__ float g_hr[(size_t)BQ*REP];
__device__ float g_hc[(size_t)BQ*REP];
// transposed operands for (N,K) B layout
__device__ float g_svT[(size_t)CC*MS];
__device__ float g_w6c[(size_t)REP*FIN];
__device__ float g_w6r[(size_t)REP*FIN];
__device__ float g_w7c[(size_t)REP*REP];
__device__ float g_w7r[(size_t)REP*REP];

// ---------------- mma.sync helpers (standard PTX, no sm_103a-only features) ----------------
__device__ __forceinline__ uint32_t smem_u32(const void* p) {
    uint32_t a;
    asm("{ .reg .u64 t; cvta.to.shared.u64 t, %1; cvt.u32.u64 %0, t; }" : "=r"(a) : "l"(p));
    return a;
}
__device__ __forceinline__ void ldsm_x4(uint32_t& r0, uint32_t& r1, uint32_t& r2, uint32_t& r3, uint32_t addr) {
    asm volatile("ldmatrix.sync.aligned.m8n8.x4.shared.b16 {%0,%1,%2,%3}, [%4];"
                 : "=r"(r0), "=r"(r1), "=r"(r2), "=r"(r3) : "r"(addr));
}
__device__ __forceinline__ void ldsm_x2(uint32_t& r0, uint32_t& r1, uint32_t addr) {
    asm volatile("ldmatrix.sync.aligned.m8n8.x2.shared.b16 {%0,%1}, [%2];"
                 : "=r"(r0), "=r"(r1) : "r"(addr));
}
__device__ __forceinline__ void mma_bf16(float* c, const uint32_t* a, const uint32_t* b) {
    asm volatile("mma.sync.aligned.m16n8k16.row.col.f32.bf16.bf16.f32 "
                 "{%0,%1,%2,%3}, {%4,%5,%6,%7}, {%8,%9}, {%0,%1,%2,%3};"
                 : "+f"(c[0]), "+f"(c[1]), "+f"(c[2]), "+f"(c[3])
                 : "r"(a[0]), "r"(a[1]), "r"(a[2]), "r"(a[3]), "r"(b[0]), "r"(b[1]));
}
// fp32 -> (hi, lo) bf16 pair packed as 2 adjacent elements into a u32
__device__ __forceinline__ void pack_hilo(float f0, float f1, uint32_t& hi, uint32_t& lo) {
    __nv_bfloat16 h0 = __float2bfloat16_rn(f0);
    __nv_bfloat16 h1 = __float2bfloat16_rn(f1);
    __nv_bfloat16 l0 = __float2bfloat16_rn(f0 - __bfloat162float(h0));
    __nv_bfloat16 l1 = __float2bfloat16_rn(f1 - __bfloat162float(h1));
    hi = (uint32_t)__bfloat16_as_ushort(h0) | ((uint32_t)__bfloat16_as_ushort(h1) << 16);
    lo = (uint32_t)__bfloat16_as_ushort(l0) | ((uint32_t)__bfloat16_as_ushort(l1) << 16);
}

// ================= HMMA GEMM: C(M,N) = A(M,K) @ B(N,K)^T =================
// CTA: 256 threads (8 warps, 2x4), tile 128x128, BK=32.
// bf16 hi/lo split, 3 mma per (hi,lo) combo: hh + hl + lh.
// AMODE 0: A row-major (M,K). AMODE 1: A = im2col of NCHW X, k = ci*9 + kh*3 + kw.
// B always (N,K) row-major. M%128==0, N%128==0, K%32==0 at every call site.
#define SPAD 40
template<int AMODE, bool BIAS, bool RELU>
__global__ __launch_bounds__(256)
void mma_gemm(const float* __restrict__ A, const float* __restrict__ B,
              const float* __restrict__ bias, float* __restrict__ C,
              int M, int N, int K, int Cin, int HW, int Hd, int Wd)
{
    __shared__ __nv_bfloat16 Ah[128][SPAD], Al[128][SPAD];
    __shared__ __nv_bfloat16 Bh[128][SPAD], Bl[128][SPAD];

    const int tid  = threadIdx.x;
    const int wid  = tid >> 5;
    const int lane = tid & 31;
    const int warp_m = wid & 1;      // 2
    const int warp_n = wid >> 1;     // 4
    const size_t m0 = (size_t)blockIdx.y * 128;
    const size_t n0 = (size_t)blockIdx.x * 128;

    // staging mapping: 256 threads cover 128 rows x 32 k as (row, 16-k half)
    const int srow = tid & 127;
    const int sk0  = (tid >> 7) * 16;

    // conv decode (fixed per thread)
    int oh = 0, ow = 0;
    const float* xb = A;
    if (AMODE == 1) {
        const int m = (int)(m0 + srow);
        const int nimg = m / HW;
        const int pp = m - nimg * HW;
        oh = pp / Wd;
        ow = pp - oh * Wd;
        xb = A + (size_t)nimg * Cin * HW;
    }

    float acc[4][4][4];
    #pragma unroll
    for (int a = 0; a < 4; a++)
        #pragma unroll
        for (int b = 0; b < 4; b++)
            #pragma unroll
            for (int c = 0; c < 4; c++) acc[a][b][c] = 0.f;

    for (int k0 = 0; k0 < K; k0 += 32) {
        // ---- stage A (128 x 32) ----
        {
            float f[16];
            if (AMODE == 0) {
                const float4* pa = (const float4*)(A + (m0 + srow) * (size_t)K + k0 + sk0);
                float4 v0 = pa[0], v1 = pa[1], v2 = pa[2], v3 = pa[3];
                f[0]=v0.x; f[1]=v0.y; f[2]=v0.z; f[3]=v0.w;
                f[4]=v1.x; f[5]=v1.y; f[6]=v1.z; f[7]=v1.w;
                f[8]=v2.x; f[9]=v2.y; f[10]=v2.z; f[11]=v2.w;
                f[12]=v3.x; f[13]=v3.y; f[14]=v3.z; f[15]=v3.w;
            } else {
                #pragma unroll 4
                for (int j = 0; j < 16; j++) {
                    const int k  = k0 + sk0 + j;
                    const int ci = k / 9;
                    const int r9 = k - ci * 9;
                    const int kh = r9 / 3;
                    const int kw = r9 - kh * 3;
                    const int ih = oh + kh - 1;
                    const int iw = ow + kw - 1;
                    f[j] = (ih >= 0 && ih < Hd && iw >= 0 && iw < Wd)
                           ? xb[(size_t)ci * HW + ih * Wd + iw] : 0.f;
                }
            }
            #pragma unroll
            for (int j = 0; j < 16; j += 2) {
                uint32_t hi, lo;
                pack_hilo(f[j], f[j+1], hi, lo);
                *(uint32_t*)&Ah[srow][sk0 + j] = hi;
                *(uint32_t*)&Al[srow][sk0 + j] = lo;
            }
        }
        // ---- stage B (128 x 32) ----
        {
            const float4* pb = (const float4*)(B + (n0 + srow) * (size_t)K + k0 + sk0);
            float4 v0 = pb[0], v1 = pb[1], v2 = pb[2], v3 = pb[3];
            float f[16] = {v0.x,v0.y,v0.z,v0.w, v1.x,v1.y,v1.z,v1.w,
                           v2.x,v2.y,v2.z,v2.w, v3.x,v3.y,v3.z,v3.w};
            #pragma unroll
            for (int j = 0; j < 16; j += 2) {
                uint32_t hi, lo;
                pack_hilo(f[j], f[j+1], hi, lo);
                *(uint32_t*)&Bh[srow][sk0 + j] = hi;
                *(uint32_t*)&Bl[srow][sk0 + j] = lo;
            }
        }
        __syncthreads();

        // ---- two k16 steps ----
        #pragma unroll
        for (int ks = 0; ks < 2; ks++) {
            const int kk = ks * 16;
            // B fragments: 4 n-tiles of 8
            uint32_t bh[4][2], bl[4][2];
            {
                const int brow = warp_n * 32 + (lane & 7);
                const int bcol = kk + ((lane >> 3) & 1) * 8;
                #pragma unroll
                for (int nt = 0; nt < 4; nt++) {
                    ldsm_x2(bh[nt][0], bh[nt][1], smem_u32(&Bh[brow + nt * 8][bcol]));
                    ldsm_x2(bl[nt][0], bl[nt][1], smem_u32(&Bl[brow + nt * 8][bcol]));
                }
            }
            // A fragments per m-tile, then 12 mmas
            const int arow = warp_m * 64 + (lane & 15);
            const int acol = kk + (lane >> 4) * 8;
            #pragma unroll
            for (int mt = 0; mt < 4; mt++) {
                uint32_t ah[4], al[4];
                ldsm_x4(ah[0], ah[1], ah[2], ah[3], smem_u32(&Ah[arow + mt * 16][acol]));
                ldsm_x4(al[0], al[1], al[2], al[3], smem_u32(&Al[arow + mt * 16][acol]));
                #pragma unroll
                for (int nt = 0; nt < 4; nt++) {
                    mma_bf16(acc[mt][nt], ah, bh[nt]);   // hi*hi
                    mma_bf16(acc[mt][nt], ah, bl[nt]);   // hi*lo
                    mma_bf16(acc[mt][nt], al, bh[nt]);   // lo*hi
                }
            }
        }
        __syncthreads();
    }

    // ---- epilogue ----
    const int g = lane >> 2;
    const int cl = (lane & 3) * 2;
    #pragma unroll
    for (int mt = 0; mt < 4; mt++) {
        const size_t r0 = m0 + warp_m * 64 + mt * 16 + g;
        #pragma unroll
        for (int nt = 0; nt < 4; nt++) {
            const size_t cidx = n0 + warp_n * 32 + nt * 8 + cl;
            float2 v0 = make_float2(acc[mt][nt][0], acc[mt][nt][1]);
            float2 v1 = make_float2(acc[mt][nt][2], acc[mt][nt][3]);
            if (BIAS) {
                const float b0 = bias[cidx], b1 = bias[cidx + 1];
                v0.x += b0; v0.y += b1; v1.x += b0; v1.y += b1;
            }
            if (RELU) {
                v0.x = fmaxf(v0.x, 0.f); v0.y = fmaxf(v0.y, 0.f);
                v1.x = fmaxf(v1.x, 0.f); v1.y = fmaxf(v1.y, 0.f);
            }
            *(float2*)(C + r0 * N + cidx) = v0;
            *(float2*)(C + (r0 + 8) * N + cidx) = v1;
        }
    }
}

// ---------------- fp32 tiled transpose: dst(C,R) = src(R,C)^T ----------------
__global__ void transpose32(const float* __restrict__ src, float* __restrict__ dst, int R, int C)
{
    __shared__ float t[32][33];
    const int c0 = blockIdx.x * 32, r0 = blockIdx.y * 32;
    const int tx = threadIdx.x, ty = threadIdx.y;   // (32, 8)
    for (int i = ty; i < 32; i += 8)
        t[i][tx] = src[(size_t)(r0 + i) * C + c0 + tx];
    __syncthreads();
    for (int i = ty; i < 32; i += 8)
        dst[(size_t)(c0 + i) * R + r0 + tx] = t[tx][i];
}

// ---------------- sup spatial mean ----------------
__global__ void gap_mean_kernel(const float* __restrict__ sup, float* __restrict__ out)
{
    const int gw = (blockIdx.x * blockDim.x + threadIdx.x) >> 5;
    const int lane = threadIdx.x & 31;
    if (gw >= SS*CC) return;
    const float* pch = sup + (size_t)gw * HWS;
    float s = 0.f;
    for (int i = lane; i < HWS; i += 32) s += pch[i];
    #pragma unroll
    for (int o = 16; o; o >>= 1) s += __shfl_xor_sync(0xffffffffu, s, o);
    if (lane == 0) out[gw] = s * (1.f / 256.f);
}

// ---------------- gap "convs" (center tap; names swapped per reference) ----------------
__global__ __launch_bounds__(256)
void gap_fc_kernel(const float* __restrict__ gapin,
                   const float* __restrict__ gkw, const float* __restrict__ gkb,
                   const float* __restrict__ gvw, const float* __restrict__ gvb,
                   float* __restrict__ gapval, float* __restrict__ gapkey)
{
    const int s = blockIdx.x;
    const int co = threadIdx.x;
    __shared__ float gin[CC];
    gin[co] = gapin[s*CC + co];
    __syncthreads();
    float a = gkb[co], b = gvb[co];
    for (int ci = 0; ci < CC; ci++) {
        const float g = gin[ci];
        a += g * gkw[(size_t)(co*CC + ci)*9 + 4];
        b += g * gvw[(size_t)(co*CC + ci)*9 + 4];
    }
    gapval[s*CC + co] = a;
    gapkey[s*CC + co] = b;
}

// ---------------- row softmax over N=5120 (in place) ----------------
__global__ __launch_bounds__(256)
void softmax_rows(float* __restrict__ S, int N)
{
    const int m = blockIdx.x;
    float* row = S + (size_t)m * N;
    __shared__ float sm[32];
    __shared__ float bcast;
    const int tid = threadIdx.x, lane = tid & 31, w = tid >> 5;

    float mx = -1e30f;
    for (int i = tid; i < N; i += 256) mx = fmaxf(mx, row[i]);
    #pragma unroll
    for (int o = 16; o; o >>= 1) mx = fmaxf(mx, __shfl_xor_sync(0xffffffffu, mx, o));
    if (lane == 0) sm[w] = mx;
    __syncthreads();
    if (tid < 32) {
        float v = (tid < 8) ? sm[tid] : -1e30f;
        #pragma unroll
        for (int o = 16; o; o >>= 1) v = fmaxf(v, __shfl_xor_sync(0xffffffffu, v, o));
        if (tid == 0) bcast = v;
    }
    __syncthreads();
    mx = bcast;
    __syncthreads();

    float sum = 0.f;
    for (int i = tid; i < N; i += 256) {
        float e = expf(row[i] - mx);
        row[i] = e;
        sum += e;
    }
    #pragma unroll
    for (int o = 16; o; o >>= 1) sum += __shfl_xor_sync(0xffffffffu, sum, o);
    if (lane == 0) sm[w] = sum;
    __syncthreads();
    if (tid < 32) {
        float v = (tid < 8) ? sm[tid] : 0.f;
        #pragma unroll
        for (int o = 16; o; o >>= 1) v += __shfl_xor_sync(0xffffffffu, v, o);
        if (tid == 0) bcast = v;
    }
    __syncthreads();
    const float inv = 1.f / bcast;
    for (int i = tid; i < N; i += 256) row[i] *= inv;
}

// ---------------- fused channel attention ----------------
__global__ __launch_bounds__(256)
void chl_attn_kernel(const float* __restrict__ qk, const float* __restrict__ gapkey,
                     const float* __restrict__ gapval, float* __restrict__ out)
{
    const int m = blockIdx.x;
    __shared__ float qrow[CC];
    __shared__ float pr[SS];
    const int tid = threadIdx.x;
    qrow[tid] = qk[(size_t)m*CC + tid];
    __syncthreads();
    if (tid < SS) {
        const float* krow = gapkey + tid*CC;
        float acc = 0.f;
        #pragma unroll 8
        for (int i = 0; i < CC; i++) acc += qrow[i] * krow[i];
        pr[tid] = acc;
    }
    __syncthreads();
    if (tid == 0) {
        float mx = -1e30f;
        #pragma unroll
        for (int s = 0; s < SS; s++) mx = fmaxf(mx, pr[s]);
        float sum = 0.f;
        #pragma unroll
        for (int s = 0; s < SS; s++) { float e = expf(pr[s] - mx); pr[s] = e; sum += e; }
        const float inv = 1.f / sum;
        #pragma unroll
        for (int s = 0; s < SS; s++) pr[s] *= inv;
    }
    __syncthreads();
    float acc = 0.f;
    #pragma unroll
    for (int s = 0; s < SS; s++) acc += pr[s] * gapval[s*CC + tid];
    out[(size_t)m*CC + tid] = acc;
}

// ---------------- NHWC(3 sources) -> NCHW pack (HW=49) ----------------
__global__ void nhwc_to_nchw3(float* __restrict__ dst,
                              const float* __restrict__ s0,
                              const float* __restrict__ s1,
                              const float* __restrict__ s2, int Ctot)
{
    __shared__ float tile[49][33];
    const int b = blockIdx.x, cg = blockIdx.y;
    const int tx = threadIdx.x, ty = threadIdx.y;   // (32, 8)
    const int c = cg*32 + tx;
    const float* src = (c < 256) ? s0 : ((c < 512) ? s1 : s2);
    const int cl = c & 255;
    for (int p = ty; p < 49; p += 8)
        tile[p][tx] = src[((size_t)b*49 + p)*256 + cl];
    __syncthreads();
    for (int cc = ty; cc < 32; cc += 8) {
        float* drow = dst + ((size_t)b*Ctot + cg*32 + cc) * 49;
        drow[tx] = tile[tx][cc];
        if (tx + 32 < 49) drow[tx + 32] = tile[tx + 32][cc];
    }
}

// ---------------- launch ----------------
extern "C" void kernel_launch(void* const* d_in, const int* in_sizes, int n_in,
                              void* d_out, int out_size)
{
    const float* x     = (const float*)d_in[0];
    const float* sup   = (const float*)d_in[1];
    const float* qv_w  = (const float*)d_in[2];
    const float* qv_b  = (const float*)d_in[3];
    const float* qk_w  = (const float*)d_in[4];
    const float* qk_b  = (const float*)d_in[5];
    const float* gk_w  = (const float*)d_in[6];
    const float* gk_b  = (const float*)d_in[7];
    const float* gv_w  = (const float*)d_in[8];
    const float* gv_b  = (const float*)d_in[9];
    const float* sv_w  = (const float*)d_in[10];
    const float* sv_b  = (const float*)d_in[11];
    const float* sk_w  = (const float*)d_in[12];
    const float* sk_b  = (const float*)d_in[13];
    const float* cat_w = (const float*)d_in[14];
    const float* cat_b = (const float*)d_in[15];
    const float* fc6c_w = (const float*)d_in[16];
    const float* fc6c_b = (const float*)d_in[17];
    const float* fc7c_w = (const float*)d_in[18];
    const float* fc7c_b = (const float*)d_in[19];
    const float* fc6r_w = (const float*)d_in[20];
    const float* fc6r_b = (const float*)d_in[21];
    const float* fc7r_w = (const float*)d_in[22];
    const float* fc7r_b = (const float*)d_in[23];
    float* out = (float*)d_out;

    float *p_qv, *p_qk, *p_sv, *p_sk, *p_gapin, *p_gapval, *p_gapkey;
    float *p_S, *p_attn, *p_attnchl, *p_catin, *p_fnhwc, *p_fuse, *p_hr, *p_hc;
    float *p_svT, *p_w6c, *p_w6r, *p_w7c, *p_w7r;
    cudaGetSymbolAddress((void**)&p_qv, g_qv);
    cudaGetSymbolAddress((void**)&p_qk, g_qk);
    cudaGetSymbolAddress((void**)&p_sv, g_sv);
    cudaGetSymbolAddress((void**)&p_sk, g_sk);
    cudaGetSymbolAddress((void**)&p_gapin, g_gapin);
    cudaGetSymbolAddress((void**)&p_gapval, g_gapval);
    cudaGetSymbolAddress((void**)&p_gapkey, g_gapkey);
    cudaGetSymbolAddress((void**)&p_S, g_S);
    cudaGetSymbolAddress((void**)&p_attn, g_attn);
    cudaGetSymbolAddress((void**)&p_attnchl, g_attnchl);
    cudaGetSymbolAddress((void**)&p_catin, g_catin);
    cudaGetSymbolAddress((void**)&p_fnhwc, g_fuse_nhwc);
    cudaGetSymbolAddress((void**)&p_fuse, g_fuse);
    cudaGetSymbolAddress((void**)&p_hr, g_hr);
    cudaGetSymbolAddress((void**)&p_hc, g_hc);
    cudaGetSymbolAddress((void**)&p_svT, g_svT);
    cudaGetSymbolAddress((void**)&p_w6c, g_w6c);
    cudaGetSymbolAddress((void**)&p_w6r, g_w6r);
    cudaGetSymbolAddress((void**)&p_w7c, g_w7c);
    cudaGetSymbolAddress((void**)&p_w7r, g_w7r);

    // 0) weight transposes for (N,K) B-operand layout
    transpose32<<<dim3(REP/32, FIN/32), dim3(32,8)>>>(fc6c_w, p_w6c, FIN, REP);
    transpose32<<<dim3(REP/32, FIN/32), dim3(32,8)>>>(fc6r_w, p_w6r, FIN, REP);
    transpose32<<<dim3(REP/32, REP/32), dim3(32,8)>>>(fc7c_w, p_w7c, REP, REP);
    transpose32<<<dim3(REP/32, REP/32), dim3(32,8)>>>(fc7r_w, p_w7r, REP, REP);

    // 1) support GAP + center-tap gap convs
    gap_mean_kernel<<<(SS*CC*32 + 255)/256, 256>>>(sup, p_gapin);
    gap_fc_kernel<<<SS, 256>>>(p_gapin, gk_w, gk_b, gv_w, gv_b, p_gapval, p_gapkey);

    // 2) four 3x3 convs (HMMA implicit im2col, NHWC outputs)
    mma_gemm<1,true,false><<<dim3(CC/128, M1/128), 256>>>(x,   qv_w, qv_b, p_qv, M1, CC, CC*9, CC, HWX, HH, WWD);
    mma_gemm<1,true,false><<<dim3(CC/128, M1/128), 256>>>(x,   qk_w, qk_b, p_qk, M1, CC, CC*9, CC, HWX, HH, WWD);
    mma_gemm<1,true,false><<<dim3(CC/128, MS/128), 256>>>(sup, sv_w, sv_b, p_sv, MS, CC, CC*9, CC, HWS, 16, 16);
    mma_gemm<1,true,false><<<dim3(CC/128, MS/128), 256>>>(sup, sk_w, sk_b, p_sk, MS, CC, CC*9, CC, HWS, 16, 16);

    // sv^T for PV B-operand
    transpose32<<<dim3(CC/32, MS/32), dim3(32,8)>>>(p_sv, p_svT, MS, CC);

    // 3) similarity = qk @ sk^T, softmax rows
    mma_gemm<0,false,false><<<dim3(MS/128, M1/128), 256>>>(p_qk, p_sk, nullptr, p_S, M1, MS, CC, 0, 0, 0, 0);
    softmax_rows<<<M1, 256>>>(p_S, MS);

    // 4) channel attention (fused)
    chl_attn_kernel<<<M1, 256>>>(p_qk, p_gapkey, p_gapval, p_attnchl);

    // 5) attn = P @ sv
    mma_gemm<0,false,false><<<dim3(CC/128, M1/128), 256>>>(p_S, p_svT, nullptr, p_attn, M1, CC, MS, 0, 0, 0, 0);

    // 6) concat pack -> NCHW (B,768,7,7)
    nhwc_to_nchw3<<<dim3(BQ, CCAT/32), dim3(32,8)>>>(p_catin, p_qv, p_attn, p_attnchl, CCAT);

    // 7) cat conv (768->256) + ReLU, then pack NHWC -> (B, 12544)
    mma_gemm<1,true,true><<<dim3(CC/128, M1/128), 256>>>(p_catin, cat_w, cat_b, p_fnhwc, M1, CC, CCAT*9, CCAT, HWX, HH, WWD);
    nhwc_to_nchw3<<<dim3(BQ, CC/32), dim3(32,8)>>>(p_fuse, p_fnhwc, p_fnhwc, p_fnhwc, CC);

    // 8) FC heads: xc then xr
    mma_gemm<0,true,true><<<dim3(REP/128, BQ/128), 256>>>(p_fuse, p_w6c, fc6c_b, p_hc, BQ, REP, FIN, 0, 0, 0, 0);
    mma_gemm<0,true,true><<<dim3(REP/128, BQ/128), 256>>>(p_hc, p_w7c, fc7c_b, out, BQ, REP, REP, 0, 0, 0, 0);
    mma_gemm<0,true,true><<<dim3(REP/128, BQ/128), 256>>>(p_fuse, p_w6r, fc6r_b, p_hr, BQ, REP, FIN, 0, 0, 0, 0);
    mma_gemm<0,true,true><<<dim3(REP/128, BQ/128), 256>>>(p_hr, p_w7r, fc7r_b, out + (size_t)BQ*REP, BQ, REP, REP, 0, 0, 0, 0);
}

// round 4
// speedup vs baseline: 3.2007x; 2.7672x over previous
#include <cuda_runtime.h>
#include <cuda_bf16.h>
#include <math.h>
#include <stdint.h>

typedef unsigned short u16;

// ---------------- problem constants ----------------
#define BQ   512
#define CC   256
#define HH   7
#define WWD  7
#define HWX  49
#define M1   (BQ*HWX)      // 25088
#define SS   20
#define HWS  256
#define MS   (SS*HWS)      // 5120
#define REP  1024
#define FIN  (CC*HWX)      // 12544
#define CCAT 768
#define KX   (CC*9)        // 2304
#define KCAT (CCAT*9)      // 6912
#define NSPLIT 8

// ---------------- scratch (static device globals; no allocation) ----------------
__device__ u16 b_colx_h[(size_t)M1*KX],   b_colx_l[(size_t)M1*KX];
__device__ u16 b_colsup_h[(size_t)MS*KX], b_colsup_l[(size_t)MS*KX];
__device__ u16 b_colcat_h[(size_t)M1*KCAT], b_colcat_l[(size_t)M1*KCAT];
__device__ u16 b_wqv_h[CC*KX], b_wqv_l[CC*KX];
__device__ u16 b_wqk_h[CC*KX], b_wqk_l[CC*KX];
__device__ u16 b_wsv_h[CC*KX], b_wsv_l[CC*KX];
__device__ u16 b_wsk_h[CC*KX], b_wsk_l[CC*KX];
__device__ u16 b_wcat_h[CC*KCAT], b_wcat_l[CC*KCAT];
__device__ u16 b_w6c_h[(size_t)REP*FIN], b_w6c_l[(size_t)REP*FIN];
__device__ u16 b_w6r_h[(size_t)REP*FIN], b_w6r_l[(size_t)REP*FIN];
__device__ u16 b_w7c_h[REP*REP], b_w7c_l[REP*REP];
__device__ u16 b_w7r_h[REP*REP], b_w7r_l[REP*REP];
__device__ u16 b_qk_h[(size_t)M1*CC], b_qk_l[(size_t)M1*CC];
__device__ u16 b_sk_h[(size_t)MS*CC], b_sk_l[(size_t)MS*CC];
__device__ u16 b_svT_h[(size_t)CC*MS], b_svT_l[(size_t)CC*MS];
__device__ u16 b_Sh[(size_t)M1*MS], b_Sl[(size_t)M1*MS];
__device__ u16 b_fuse_h[(size_t)BQ*FIN], b_fuse_l[(size_t)BQ*FIN];
__device__ u16 b_hc_h[BQ*REP], b_hc_l[BQ*REP];
__device__ u16 b_hr_h[BQ*REP], b_hr_l[BQ*REP];
__device__ float g_qv[(size_t)M1*CC];
__device__ float g_qk[(size_t)M1*CC];
__device__ float g_sv[(size_t)MS*CC];
__device__ float g_S[(size_t)M1*MS];
__device__ float g_attn[(size_t)M1*CC];
__device__ float g_attnchl[(size_t)M1*CC];
__device__ float g_fnhwc[(size_t)M1*CC];
__device__ float g_part[(size_t)NSPLIT*BQ*REP];
__device__ float g_gapin[SS*CC], g_gapval[SS*CC], g_gapkey[SS*CC];

// ---------------- helpers ----------------
__device__ __forceinline__ uint32_t smem_u32(const void* p) {
    uint32_t a;
    asm("{ .reg .u64 t; cvta.to.shared.u64 t, %1; cvt.u32.u64 %0, t; }" : "=r"(a) : "l"(p));
    return a;
}
#define SWZ(o) ((o) ^ (((o) >> 3) & 0x70))
__device__ __forceinline__ void ldsm_x4(uint32_t& r0, uint32_t& r1, uint32_t& r2, uint32_t& r3, uint32_t addr) {
    asm volatile("ldmatrix.sync.aligned.m8n8.x4.shared.b16 {%0,%1,%2,%3}, [%4];"
                 : "=r"(r0), "=r"(r1), "=r"(r2), "=r"(r3) : "r"(addr));
}
__device__ __forceinline__ void ldsm_x2(uint32_t& r0, uint32_t& r1, uint32_t addr) {
    asm volatile("ldmatrix.sync.aligned.m8n8.x2.shared.b16 {%0,%1}, [%2];"
                 : "=r"(r0), "=r"(r1) : "r"(addr));
}
__device__ __forceinline__ void mma_bf16(float* c, const uint32_t* a, const uint32_t* b) {
    asm volatile("mma.sync.aligned.m16n8k16.row.col.f32.bf16.bf16.f32 "
                 "{%0,%1,%2,%3}, {%4,%5,%6,%7}, {%8,%9}, {%0,%1,%2,%3};"
                 : "+f"(c[0]), "+f"(c[1]), "+f"(c[2]), "+f"(c[3])
                 : "r"(a[0]), "r"(a[1]), "r"(a[2]), "r"(a[3]), "r"(b[0]), "r"(b[1]));
}
__device__ __forceinline__ void pack_hilo(float f0, float f1, uint32_t& hi, uint32_t& lo) {
    __nv_bfloat16 h0 = __float2bfloat16_rn(f0);
    __nv_bfloat16 h1 = __float2bfloat16_rn(f1);
    __nv_bfloat16 l0 = __float2bfloat16_rn(f0 - __bfloat162float(h0));
    __nv_bfloat16 l1 = __float2bfloat16_rn(f1 - __bfloat162float(h1));
    hi = (uint32_t)__bfloat16_as_ushort(h0) | ((uint32_t)__bfloat16_as_ushort(h1) << 16);
    lo = (uint32_t)__bfloat16_as_ushort(l0) | ((uint32_t)__bfloat16_as_ushort(l1) << 16);
}
__device__ __forceinline__ void hilo1(float f, u16& h, u16& l) {
    __nv_bfloat16 hb = __float2bfloat16_rn(f);
    __nv_bfloat16 lb = __float2bfloat16_rn(f - __bfloat162float(hb));
    h = __bfloat16_as_ushort(hb); l = __bfloat16_as_ushort(lb);
}
#define CPA(dst, src) asm volatile("cp.async.cg.shared.global [%0], [%1], 16;\n" :: "r"(dst), "l"(src))
#define CP_COMMIT()   asm volatile("cp.async.commit_group;\n" ::: "memory")
template<int NN> __device__ __forceinline__ void cp_wait() {
    asm volatile("cp.async.wait_group %0;\n" :: "n"(NN) : "memory");
}

// ================= bf16 hi/lo HMMA GEMM: C(M,N) = A(M,K) @ B(N,K)^T =================
// 256 thr (8 warps 2x4), CTA 128x128, BK=32, cp.async double-buffered, swizzled smem.
// OUTMODE: bit0 fp32 C, bit1 hi/lo bf16 C. Split-K via gridDim.z (f32 partials, no bias).
#define TC_SMEM (65536 + 1024)
template<int OUTMODE, bool BIAS, bool RELU>
__global__ __launch_bounds__(256, 2)
void hgemm(const u16* __restrict__ Ah, const u16* __restrict__ Al,
           const u16* __restrict__ Bh, const u16* __restrict__ Bl,
           const float* __restrict__ bias,
           float* __restrict__ Cf, u16* __restrict__ Ch, u16* __restrict__ Cl,
           int M, int N, int K)
{
    extern __shared__ char dsm_raw[];
    const uint32_t raw = smem_u32(dsm_raw);
    const uint32_t sbase = (raw + 127u) & ~127u;
    char* sm0 = dsm_raw + (sbase - raw);
    // layout: [buf][arr] each 8KB: arr 0=Ah 1=Al 2=Bh 3=Bl
    uint32_t sb[2][4];
    #pragma unroll
    for (int b = 0; b < 2; b++)
        #pragma unroll
        for (int a = 0; a < 4; a++) sb[b][a] = sbase + (b*4 + a) * 8192;

    const int tid = threadIdx.x, wid = tid >> 5, lane = tid & 31;
    const int warp_m = wid & 1, warp_n = wid >> 1;
    const size_t m0 = (size_t)blockIdx.y * 128;
    const size_t n0 = (size_t)blockIdx.x * 128;
    const int kLen = K / gridDim.z;
    const int kbeg = blockIdx.z * kLen;
    const int nCh = kLen >> 5;

    // loader: 2 chunks of 16B per thread per array
    const int l_row[2] = { (tid + 0) >> 2, (tid + 256) >> 2 };
    const int l_c16[2] = { tid & 3, tid & 3 };
    uint32_t l_sw[2];
    #pragma unroll
    for (int r = 0; r < 2; r++) l_sw[r] = SWZ((uint32_t)(l_row[r]*64 + l_c16[r]*16));

    float acc[4][4][4];
    #pragma unroll
    for (int a = 0; a < 4; a++)
        #pragma unroll
        for (int b = 0; b < 4; b++)
            #pragma unroll
            for (int c = 0; c < 4; c++) acc[a][b][c] = 0.f;

    // prologue load
    {
        const int k0 = kbeg;
        #pragma unroll
        for (int r = 0; r < 2; r++) {
            const size_t ga = (m0 + l_row[r]) * (size_t)K + k0 + l_c16[r]*8;
            const size_t gb = (n0 + l_row[r]) * (size_t)K + k0 + l_c16[r]*8;
            CPA(sb[0][0] + l_sw[r], Ah + ga);
            CPA(sb[0][1] + l_sw[r], Al + ga);
            CPA(sb[0][2] + l_sw[r], Bh + gb);
            CPA(sb[0][3] + l_sw[r], Bl + gb);
        }
        CP_COMMIT();
    }

    for (int ch = 0; ch < nCh; ++ch) {
        const int buf = ch & 1;
        if (ch + 1 < nCh) {
            const int k0 = kbeg + (ch + 1) * 32;
            const int nb = buf ^ 1;
            #pragma unroll
            for (int r = 0; r < 2; r++) {
                const size_t ga = (m0 + l_row[r]) * (size_t)K + k0 + l_c16[r]*8;
                const size_t gb = (n0 + l_row[r]) * (size_t)K + k0 + l_c16[r]*8;
                CPA(sb[nb][0] + l_sw[r], Ah + ga);
                CPA(sb[nb][1] + l_sw[r], Al + ga);
                CPA(sb[nb][2] + l_sw[r], Bh + gb);
                CPA(sb[nb][3] + l_sw[r], Bl + gb);
            }
            CP_COMMIT();
            cp_wait<1>();
        } else {
            cp_wait<0>();
        }
        __syncthreads();

        #pragma unroll
        for (int ks = 0; ks < 2; ks++) {
            const uint32_t kk2 = ks * 32;               // byte offset of k16 group
            uint32_t bh[4][2], bl[4][2];
            const int brow = warp_n * 32 + (lane & 7);
            const uint32_t bbyte = kk2 + ((lane >> 3) & 1) * 16;
            #pragma unroll
            for (int nt = 0; nt < 4; nt++) {
                const uint32_t off = SWZ((uint32_t)((brow + nt*8)*64) + bbyte);
                ldsm_x2(bh[nt][0], bh[nt][1], sb[buf][2] + off);
                ldsm_x2(bl[nt][0], bl[nt][1], sb[buf][3] + off);
            }
            const int arow = warp_m * 64 + (lane & 15);
            const uint32_t abyte = kk2 + (lane >> 4) * 16;
            #pragma unroll
            for (int mt = 0; mt < 4; mt++) {
                const uint32_t off = SWZ((uint32_t)((arow + mt*16)*64) + abyte);
                uint32_t ah[4], al[4];
                ldsm_x4(ah[0], ah[1], ah[2], ah[3], sb[buf][0] + off);
                ldsm_x4(al[0], al[1], al[2], al[3], sb[buf][1] + off);
                #pragma unroll
                for (int nt = 0; nt < 4; nt++) {
                    mma_bf16(acc[mt][nt], ah, bh[nt]);
                    mma_bf16(acc[mt][nt], ah, bl[nt]);
                    mma_bf16(acc[mt][nt], al, bh[nt]);
                }
            }
        }
        __syncthreads();
    }

    // epilogue
    float* Cfo = Cf + (size_t)blockIdx.z * (size_t)M * N;
    const int g = lane >> 2;
    const int cl2 = (lane & 3) * 2;
    #pragma unroll
    for (int mt = 0; mt < 4; mt++) {
        const size_t r0 = m0 + warp_m*64 + mt*16 + g;
        #pragma unroll
        for (int nt = 0; nt < 4; nt++) {
            const size_t cidx = n0 + warp_n*32 + nt*8 + cl2;
            float2 v0 = make_float2(acc[mt][nt][0], acc[mt][nt][1]);
            float2 v1 = make_float2(acc[mt][nt][2], acc[mt][nt][3]);
            if (BIAS) {
                const float b0 = bias[cidx], b1 = bias[cidx + 1];
                v0.x += b0; v0.y += b1; v1.x += b0; v1.y += b1;
            }
            if (RELU) {
                v0.x = fmaxf(v0.x, 0.f); v0.y = fmaxf(v0.y, 0.f);
                v1.x = fmaxf(v1.x, 0.f); v1.y = fmaxf(v1.y, 0.f);
            }
            if (OUTMODE & 1) {
                *(float2*)(Cfo + r0 * N + cidx) = v0;
                *(float2*)(Cfo + (r0 + 8) * N + cidx) = v1;
            }
            if (OUTMODE & 2) {
                uint32_t h0, l0, h1, l1;
                pack_hilo(v0.x, v0.y, h0, l0);
                pack_hilo(v1.x, v1.y, h1, l1);
                *(uint32_t*)&Ch[r0 * N + cidx] = h0;
                *(uint32_t*)&Cl[r0 * N + cidx] = l0;
                *(uint32_t*)&Ch[(r0 + 8) * N + cidx] = h1;
                *(uint32_t*)&Cl[(r0 + 8) * N + cidx] = l1;
            }
        }
    }
}

// ---------------- split-K reduce (+bias +relu), fp32 or hi/lo output ----------------
template<bool HILO>
__global__ void reduce_splitk(const float* __restrict__ part, const float* __restrict__ bias,
                              float* __restrict__ outf, u16* __restrict__ oh, u16* __restrict__ ol,
                              int MN, int N)
{
    const int i = (blockIdx.x * 256 + threadIdx.x) * 4;
    if (i >= MN) return;
    float4 s = *(const float4*)(part + i);
    #pragma unroll
    for (int sp = 1; sp < NSPLIT; sp++) {
        float4 p = *(const float4*)(part + (size_t)sp * MN + i);
        s.x += p.x; s.y += p.y; s.z += p.z; s.w += p.w;
    }
    const int n = i & (N - 1);
    s.x = fmaxf(s.x + bias[n], 0.f);
    s.y = fmaxf(s.y + bias[n+1], 0.f);
    s.z = fmaxf(s.z + bias[n+2], 0.f);
    s.w = fmaxf(s.w + bias[n+3], 0.f);
    if (HILO) {
        uint32_t h0, l0, h1, l1;
        pack_hilo(s.x, s.y, h0, l0);
        pack_hilo(s.z, s.w, h1, l1);
        *(uint2*)&oh[i] = make_uint2(h0, h1);
        *(uint2*)&ol[i] = make_uint2(l0, l1);
    } else {
        *(float4*)(outf + i) = s;
    }
}

// ---------------- elementwise fp32 -> hi/lo ----------------
__global__ void cvt_hilo(const float* __restrict__ src, u16* __restrict__ h, u16* __restrict__ l, int n4)
{
    const int i = blockIdx.x * 256 + threadIdx.x;
    if (i >= n4) return;
    float4 v = ((const float4*)src)[i];
    uint32_t h0, l0, h1, l1;
    pack_hilo(v.x, v.y, h0, l0);
    pack_hilo(v.z, v.w, h1, l1);
    ((uint2*)h)[i] = make_uint2(h0, h1);
    ((uint2*)l)[i] = make_uint2(l0, l1);
}

// ---------------- fp32 (R,C) -> hi/lo (C,R) transpose+convert ----------------
__global__ void transpose_cvt(const float* __restrict__ src, u16* __restrict__ dh, u16* __restrict__ dl,
                              int R, int C)
{
    __shared__ float t[32][33];
    const int c0 = blockIdx.x * 32, r0 = blockIdx.y * 32;
    const int tx = threadIdx.x, ty = threadIdx.y;   // (32,8)
    for (int i = ty; i < 32; i += 8)
        t[i][tx] = src[(size_t)(r0 + i) * C + c0 + tx];
    __syncthreads();
    for (int i = ty; i < 32; i += 8) {
        u16 h, l; hilo1(t[tx][i], h, l);
        const size_t o = (size_t)(c0 + i) * R + r0 + tx;
        dh[o] = h; dl[o] = l;
    }
}

// ---------------- im2col (3x3 SAME) from NCHW fp32 -> hi/lo (M, Cin*9) ----------------
__global__ void im2col_cvt(const float* __restrict__ X, u16* __restrict__ oh_, u16* __restrict__ ol_,
                           int Mr, int Cin, int HW, int Hd, int Wd)
{
    const int K = Cin * 9;
    const size_t idx = (size_t)blockIdx.x * 256 + threadIdx.x;
    const size_t tot = (size_t)Mr * (K >> 2);
    if (idx >= tot) return;
    const int Kq = K >> 2;
    const int m = (int)(idx / Kq);
    const int k0 = (int)(idx % Kq) * 4;
    const int b = m / HW, p = m - b * HW;
    const int oh = p / Wd, ow = p - oh * Wd;
    const float* xb = X + (size_t)b * Cin * HW;
    u16 hs[4], ls[4];
    #pragma unroll
    for (int j = 0; j < 4; j++) {
        const int k = k0 + j;
        const int ci = k / 9, t = k - ci * 9;
        const int dh = t / 3, dw = t - dh * 3;
        const int ih = oh + dh - 1, iw = ow + dw - 1;
        float v = (ih >= 0 && ih < Hd && iw >= 0 && iw < Wd) ? xb[(size_t)ci * HW + ih * Wd + iw] : 0.f;
        hilo1(v, hs[j], ls[j]);
    }
    const size_t o = (size_t)m * K + k0;
    *(uint2*)&oh_[o] = make_uint2((uint32_t)hs[0] | ((uint32_t)hs[1] << 16),
                                  (uint32_t)hs[2] | ((uint32_t)hs[3] << 16));
    *(uint2*)&ol_[o] = make_uint2((uint32_t)ls[0] | ((uint32_t)ls[1] << 16),
                                  (uint32_t)ls[2] | ((uint32_t)ls[3] << 16));
}

// ---------------- im2col of the 768-channel concat, direct from 3 NHWC sources ----------------
__global__ void im2col_cat_cvt(const float* __restrict__ s0, const float* __restrict__ s1,
                               const float* __restrict__ s2,
                               u16* __restrict__ oh_, u16* __restrict__ ol_)
{
    const int K = KCAT;
    const size_t idx = (size_t)blockIdx.x * 256 + threadIdx.x;
    const size_t tot = (size_t)M1 * (K >> 2);
    if (idx >= tot) return;
    const int Kq = K >> 2;
    const int m = (int)(idx / Kq);
    const int k0 = (int)(idx % Kq) * 4;
    const int b = m / HWX, p = m - b * HWX;
    const int oh = p / WWD, ow = p - oh * WWD;
    u16 hs[4], ls[4];
    #pragma unroll
    for (int j = 0; j < 4; j++) {
        const int k = k0 + j;
        const int c = k / 9, t = k - c * 9;
        const int dh = t / 3, dw = t - dh * 3;
        const int ih = oh + dh - 1, iw = ow + dw - 1;
        float v = 0.f;
        if (ih >= 0 && ih < HH && iw >= 0 && iw < WWD) {
            const float* src = (c < 256) ? s0 : ((c < 512) ? s1 : s2);
            v = src[((size_t)(b * HWX + ih * WWD + iw)) * 256 + (c & 255)];
        }
        hilo1(v, hs[j], ls[j]);
    }
    const size_t o = (size_t)m * K + k0;
    *(uint2*)&oh_[o] = make_uint2((uint32_t)hs[0] | ((uint32_t)hs[1] << 16),
                                  (uint32_t)hs[2] | ((uint32_t)hs[3] << 16));
    *(uint2*)&ol_[o] = make_uint2((uint32_t)ls[0] | ((uint32_t)ls[1] << 16),
                                  (uint32_t)ls[2] | ((uint32_t)ls[3] << 16));
}

// ---------------- NHWC fp32 -> NCHW-flat hi/lo (fuse) ----------------
__global__ void pack_fuse(const float* __restrict__ src, u16* __restrict__ fh, u16* __restrict__ fl)
{
    __shared__ float tile[49][33];
    const int b = blockIdx.x, cg = blockIdx.y;
    const int tx = threadIdx.x, ty = threadIdx.y;   // (32,8)
    for (int p = ty; p < 49; p += 8)
        tile[p][tx] = src[((size_t)b*49 + p)*256 + cg*32 + tx];
    __syncthreads();
    for (int cc = ty; cc < 32; cc += 8) {
        const size_t base = (size_t)b * FIN + (cg*32 + cc) * 49;
        u16 h, l;
        hilo1(tile[tx][cc], h, l);
        fh[base + tx] = h; fl[base + tx] = l;
        if (tx + 32 < 49) {
            hilo1(tile[tx + 32][cc], h, l);
            fh[base + tx + 32] = h; fl[base + tx + 32] = l;
        }
    }
}

// ---------------- sup spatial mean ----------------
__global__ void gap_mean_kernel(const float* __restrict__ sup, float* __restrict__ out)
{
    const int gw = (blockIdx.x * blockDim.x + threadIdx.x) >> 5;
    const int lane = threadIdx.x & 31;
    if (gw >= SS*CC) return;
    const float* pch = sup + (size_t)gw * HWS;
    float s = 0.f;
    for (int i = lane; i < HWS; i += 32) s += pch[i];
    #pragma unroll
    for (int o = 16; o; o >>= 1) s += __shfl_xor_sync(0xffffffffu, s, o);
    if (lane == 0) out[gw] = s * (1.f / 256.f);
}

// ---------------- gap "convs" (center tap; key/value names swapped per reference) ----------------
__global__ __launch_bounds__(256)
void gap_fc_kernel(const float* __restrict__ gapin,
                   const float* __restrict__ gkw, const float* __restrict__ gkb,
                   const float* __restrict__ gvw, const float* __restrict__ gvb,
                   float* __restrict__ gapval, float* __restrict__ gapkey)
{
    const int s = blockIdx.x;
    const int co = threadIdx.x;
    __shared__ float gin[CC];
    gin[co] = gapin[s*CC + co];
    __syncthreads();
    float a = gkb[co], b = gvb[co];
    for (int ci = 0; ci < CC; ci++) {
        const float g = gin[ci];
        a += g * gkw[(size_t)(co*CC + ci)*9 + 4];
        b += g * gvw[(size_t)(co*CC + ci)*9 + 4];
    }
    gapval[s*CC + co] = a;
    gapkey[s*CC + co] = b;
}

// ---------------- row softmax (N=5120), single global read, hi/lo bf16 out ----------------
__global__ __launch_bounds__(256)
void softmax_hilo(const float* __restrict__ S, u16* __restrict__ Sh, u16* __restrict__ Sl)
{
    __shared__ float row[MS];
    __shared__ float sm[32];
    __shared__ float bcast;
    const int m = blockIdx.x;
    const int tid = threadIdx.x, lane = tid & 31, w = tid >> 5;
    const float* g = S + (size_t)m * MS;

    float mx = -1e30f;
    for (int i = tid*4; i < MS; i += 1024) {
        float4 v = *(const float4*)(g + i);
        *(float4*)&row[i] = v;
        mx = fmaxf(fmaxf(fmaxf(mx, v.x), fmaxf(v.y, v.z)), v.w);
    }
    #pragma unroll
    for (int o = 16; o; o >>= 1) mx = fmaxf(mx, __shfl_xor_sync(0xffffffffu, mx, o));
    if (lane == 0) sm[w] = mx;
    __syncthreads();
    if (tid < 32) {
        float v = (tid < 8) ? sm[tid] : -1e30f;
        #pragma unroll
        for (int o = 16; o; o >>= 1) v = fmaxf(v, __shfl_xor_sync(0xffffffffu, v, o));
        if (tid == 0) bcast = v;
    }
    __syncthreads();
    mx = bcast;
    __syncthreads();

    float sum = 0.f;
    for (int i = tid*4; i < MS; i += 1024) {
        float4 v = *(float4*)&row[i];
        v.x = __expf(v.x - mx); v.y = __expf(v.y - mx);
        v.z = __expf(v.z - mx); v.w = __expf(v.w - mx);
        *(float4*)&row[i] = v;
        sum += v.x + v.y + v.z + v.w;
    }
    #pragma unroll
    for (int o = 16; o; o >>= 1) sum += __shfl_xor_sync(0xffffffffu, sum, o);
    if (lane == 0) sm[w] = sum;
    __syncthreads();
    if (tid < 32) {
        float v = (tid < 8) ? sm[tid] : 0.f;
        #pragma unroll
        for (int o = 16; o; o >>= 1) v += __shfl_xor_sync(0xffffffffu, v, o);
        if (tid == 0) bcast = v;
    }
    __syncthreads();
    const float inv = 1.f / bcast;
    u16* ph = Sh + (size_t)m * MS;
    u16* pl = Sl + (size_t)m * MS;
    for (int i = tid*4; i < MS; i += 1024) {
        float4 v = *(float4*)&row[i];
        uint32_t h0, l0, h1, l1;
        pack_hilo(v.x * inv, v.y * inv, h0, l0);
        pack_hilo(v.z * inv, v.w * inv, h1, l1);
        *(uint2*)&ph[i] = make_uint2(h0, h1);
        *(uint2*)&pl[i] = make_uint2(l0, l1);
    }
}

// ---------------- fused channel attention ----------------
__global__ __launch_bounds__(256)
void chl_attn_kernel(const float* __restrict__ qk, const float* __restrict__ gapkey,
                     const float* __restrict__ gapval, float* __restrict__ out)
{
    const int m = blockIdx.x;
    __shared__ float qrow[CC];
    __shared__ float pr[SS];
    const int tid = threadIdx.x;
    qrow[tid] = qk[(size_t)m*CC + tid];
    __syncthreads();
    if (tid < SS) {
        const float* krow = gapkey + tid*CC;
        float acc = 0.f;
        #pragma unroll 8
        for (int i = 0; i < CC; i++) acc += qrow[i] * krow[i];
        pr[tid] = acc;
    }
    __syncthreads();
    if (tid == 0) {
        float mx = -1e30f;
        #pragma unroll
        for (int s = 0; s < SS; s++) mx = fmaxf(mx, pr[s]);
        float sum = 0.f;
        #pragma unroll
        for (int s = 0; s < SS; s++) { float e = __expf(pr[s] - mx); pr[s] = e; sum += e; }
        const float inv = 1.f / sum;
        #pragma unroll
        for (int s = 0; s < SS; s++) pr[s] *= inv;
    }
    __syncthreads();
    float acc = 0.f;
    #pragma unroll
    for (int s = 0; s < SS; s++) acc += pr[s] * gapval[s*CC + tid];
    out[(size_t)m*CC + tid] = acc;
}

// ---------------- launch ----------------
extern "C" void kernel_launch(void* const* d_in, const int* in_sizes, int n_in,
                              void* d_out, int out_size)
{
    const float* x     = (const float*)d_in[0];
    const float* sup   = (const float*)d_in[1];
    const float* qv_w  = (const float*)d_in[2];
    const float* qv_b  = (const float*)d_in[3];
    const float* qk_w  = (const float*)d_in[4];
    const float* qk_b  = (const float*)d_in[5];
    const float* gk_w  = (const float*)d_in[6];
    const float* gk_b  = (const float*)d_in[7];
    const float* gv_w  = (const float*)d_in[8];
    const float* gv_b  = (const float*)d_in[9];
    const float* sv_w  = (const float*)d_in[10];
    const float* sv_b  = (const float*)d_in[11];
    const float* sk_w  = (const float*)d_in[12];
    const float* sk_b  = (const float*)d_in[13];
    const float* cat_w = (const float*)d_in[14];
    const float* cat_b = (const float*)d_in[15];
    const float* fc6c_w = (const float*)d_in[16];
    const float* fc6c_b = (const float*)d_in[17];
    const float* fc7c_w = (const float*)d_in[18];
    const float* fc7c_b = (const float*)d_in[19];
    const float* fc6r_w = (const float*)d_in[20];
    const float* fc6r_b = (const float*)d_in[21];
    const float* fc7r_w = (const float*)d_in[22];
    const float* fc7r_b = (const float*)d_in[23];
    float* out = (float*)d_out;

    // symbol addresses
    u16 *colx_h,*colx_l,*colsup_h,*colsup_l,*colcat_h,*colcat_l;
    u16 *wqv_h,*wqv_l,*wqk_h,*wqk_l,*wsv_h,*wsv_l,*wsk_h,*wsk_l,*wcat_h,*wcat_l;
    u16 *w6c_h,*w6c_l,*w6r_h,*w6r_l,*w7c_h,*w7c_l,*w7r_h,*w7r_l;
    u16 *qk_h,*qk_l,*sk_h,*sk_l,*svT_h,*svT_l,*Sh,*Sl,*fuse_h,*fuse_l,*hc_h,*hc_l,*hr_h,*hr_l;
    float *p_qv,*p_qk,*p_sv,*p_S,*p_attn,*p_attnchl,*p_fnhwc,*p_part,*p_gapin,*p_gapval,*p_gapkey;
    #define SYM(v, s) cudaGetSymbolAddress((void**)&v, s)
    SYM(colx_h,b_colx_h); SYM(colx_l,b_colx_l); SYM(colsup_h,b_colsup_h); SYM(colsup_l,b_colsup_l);
    SYM(colcat_h,b_colcat_h); SYM(colcat_l,b_colcat_l);
    SYM(wqv_h,b_wqv_h); SYM(wqv_l,b_wqv_l); SYM(wqk_h,b_wqk_h); SYM(wqk_l,b_wqk_l);
    SYM(wsv_h,b_wsv_h); SYM(wsv_l,b_wsv_l); SYM(wsk_h,b_wsk_h); SYM(wsk_l,b_wsk_l);
    SYM(wcat_h,b_wcat_h); SYM(wcat_l,b_wcat_l);
    SYM(w6c_h,b_w6c_h); SYM(w6c_l,b_w6c_l); SYM(w6r_h,b_w6r_h); SYM(w6r_l,b_w6r_l);
    SYM(w7c_h,b_w7c_h); SYM(w7c_l,b_w7c_l); SYM(w7r_h,b_w7r_h); SYM(w7r_l,b_w7r_l);
    SYM(qk_h,b_qk_h); SYM(qk_l,b_qk_l); SYM(sk_h,b_sk_h); SYM(sk_l,b_sk_l);
    SYM(svT_h,b_svT_h); SYM(svT_l,b_svT_l); SYM(Sh,b_Sh); SYM(Sl,b_Sl);
    SYM(fuse_h,b_fuse_h); SYM(fuse_l,b_fuse_l);
    SYM(hc_h,b_hc_h); SYM(hc_l,b_hc_l); SYM(hr_h,b_hr_h); SYM(hr_l,b_hr_l);
    SYM(p_qv,g_qv); SYM(p_qk,g_qk); SYM(p_sv,g_sv); SYM(p_S,g_S);
    SYM(p_attn,g_attn); SYM(p_attnchl,g_attnchl); SYM(p_fnhwc,g_fnhwc); SYM(p_part,g_part);
    SYM(p_gapin,g_gapin); SYM(p_gapval,g_gapval); SYM(p_gapkey,g_gapkey);

    cudaFuncSetAttribute(hgemm<1,true,false>, cudaFuncAttributeMaxDynamicSharedMemorySize, TC_SMEM);
    cudaFuncSetAttribute(hgemm<3,true,false>, cudaFuncAttributeMaxDynamicSharedMemorySize, TC_SMEM);
    cudaFuncSetAttribute(hgemm<2,true,false>, cudaFuncAttributeMaxDynamicSharedMemorySize, TC_SMEM);
    cudaFuncSetAttribute(hgemm<1,false,false>, cudaFuncAttributeMaxDynamicSharedMemorySize, TC_SMEM);
    cudaFuncSetAttribute(hgemm<1,true,true>, cudaFuncAttributeMaxDynamicSharedMemorySize, TC_SMEM);

    // 1-2: gap path
    gap_mean_kernel<<<(SS*CC*32 + 255)/256, 256>>>(sup, p_gapin);
    gap_fc_kernel<<<SS, 256>>>(p_gapin, gk_w, gk_b, gv_w, gv_b, p_gapval, p_gapkey);
    // 3-4: im2col of x and sup
    im2col_cvt<<<(int)(((size_t)M1*KX/4 + 255)/256), 256>>>(x, colx_h, colx_l, M1, CC, HWX, HH, WWD);
    im2col_cvt<<<(int)(((size_t)MS*KX/4 + 255)/256), 256>>>(sup, colsup_h, colsup_l, MS, CC, HWS, 16, 16);
    // 5-6: qv conv (launch #6 profiled)
    cvt_hilo<<<(CC*KX/4 + 255)/256, 256>>>(qv_w, wqv_h, wqv_l, CC*KX/4);
    hgemm<1,true,false><<<dim3(CC/128, M1/128), 256, TC_SMEM>>>(colx_h, colx_l, wqv_h, wqv_l, qv_b, p_qv, nullptr, nullptr, M1, CC, KX);
    // qk conv (fp32 + hilo)
    cvt_hilo<<<(CC*KX/4 + 255)/256, 256>>>(qk_w, wqk_h, wqk_l, CC*KX/4);
    hgemm<3,true,false><<<dim3(CC/128, M1/128), 256, TC_SMEM>>>(colx_h, colx_l, wqk_h, wqk_l, qk_b, p_qk, qk_h, qk_l, M1, CC, KX);
    // sv conv (fp32, transposed+cvt after)
    cvt_hilo<<<(CC*KX/4 + 255)/256, 256>>>(sv_w, wsv_h, wsv_l, CC*KX/4);
    hgemm<1,true,false><<<dim3(CC/128, MS/128), 256, TC_SMEM>>>(colsup_h, colsup_l, wsv_h, wsv_l, sv_b, p_sv, nullptr, nullptr, MS, CC, KX);
    // sk conv (hilo only)
    cvt_hilo<<<(CC*KX/4 + 255)/256, 256>>>(sk_w, wsk_h, wsk_l, CC*KX/4);
    hgemm<2,true,false><<<dim3(CC/128, MS/128), 256, TC_SMEM>>>(colsup_h, colsup_l, wsk_h, wsk_l, sk_b, nullptr, sk_h, sk_l, MS, CC, KX);
    // svT
    transpose_cvt<<<dim3(CC/32, MS/32), dim3(32,8)>>>(p_sv, svT_h, svT_l, MS, CC);
    // QK^T -> S fp32
    hgemm<1,false,false><<<dim3(MS/128, M1/128), 256, TC_SMEM>>>(qk_h, qk_l, sk_h, sk_l, nullptr, p_S, nullptr, nullptr, M1, MS, CC);
    // softmax -> hi/lo P
    softmax_hilo<<<M1, 256>>>(p_S, Sh, Sl);
    // channel attention
    chl_attn_kernel<<<M1, 256>>>(p_qk, p_gapkey, p_gapval, p_attnchl);
    // attn = P @ V
    hgemm<1,false,false><<<dim3(CC/128, M1/128), 256, TC_SMEM>>>(Sh, Sl, svT_h, svT_l, nullptr, p_attn, nullptr, nullptr, M1, CC, MS);
    // im2col of concat (direct from NHWC sources)
    im2col_cat_cvt<<<(int)(((size_t)M1*KCAT/4 + 255)/256), 256>>>(p_qv, p_attn, p_attnchl, colcat_h, colcat_l);
    // cat conv + ReLU
    cvt_hilo<<<(CC*KCAT/4 + 255)/256, 256>>>(cat_w, wcat_h, wcat_l, CC*KCAT/4);
    hgemm<1,true,true><<<dim3(CC/128, M1/128), 256, TC_SMEM>>>(colcat_h, colcat_l, wcat_h, wcat_l, cat_b, p_fnhwc, nullptr, nullptr, M1, CC, KCAT);
    // pack fuse -> hilo
    pack_fuse<<<dim3(BQ, CC/32), dim3(32,8)>>>(p_fnhwc, fuse_h, fuse_l);
    // FC heads, split-K=8
    transpose_cvt<<<dim3(REP/32, FIN/32), dim3(32,8)>>>(fc6c_w, w6c_h, w6c_l, FIN, REP);
    hgemm<1,false,false><<<dim3(REP/128, BQ/128, NSPLIT), 256, TC_SMEM>>>(fuse_h, fuse_l, w6c_h, w6c_l, nullptr, p_part, nullptr, nullptr, BQ, REP, FIN);
    reduce_splitk<true><<<(BQ*REP/4 + 255)/256, 256>>>(p_part, fc6c_b, nullptr, hc_h, hc_l, BQ*REP, REP);
    transpose_cvt<<<dim3(REP/32, REP/32), dim3(32,8)>>>(fc7c_w, w7c_h, w7c_l, REP, REP);
    hgemm<1,false,false><<<dim3(REP/128, BQ/128, NSPLIT), 256, TC_SMEM>>>(hc_h, hc_l, w7c_h, w7c_l, nullptr, p_part, nullptr, nullptr, BQ, REP, REP);
    reduce_splitk<false><<<(BQ*REP/4 + 255)/256, 256>>>(p_part, fc7c_b, out, nullptr, nullptr, BQ*REP, REP);
    transpose_cvt<<<dim3(REP/32, FIN/32), dim3(32,8)>>>(fc6r_w, w6r_h, w6r_l, FIN, REP);
    hgemm<1,false,false><<<dim3(REP/128, BQ/128, NSPLIT), 256, TC_SMEM>>>(fuse_h, fuse_l, w6r_h, w6r_l, nullptr, p_part, nullptr, nullptr, BQ, REP, FIN);
    reduce_splitk<true><<<(BQ*REP/4 + 255)/256, 256>>>(p_part, fc6r_b, nullptr, hr_h, hr_l, BQ*REP, REP);
    transpose_cvt<<<dim3(REP/32, REP/32), dim3(32,8)>>>(fc7r_w, w7r_h, w7r_l, REP, REP);
    hgemm<1,false,false><<<dim3(REP/128, BQ/128, NSPLIT), 256, TC_SMEM>>>(hr_h, hr_l, w7r_h, w7r_l, nullptr, p_part, nullptr, nullptr, BQ, REP, REP);
    reduce_splitk<false><<<(BQ*REP/4 + 255)/256, 256>>>(p_part, fc7r_b, out + (size_t)BQ*REP, nullptr, nullptr, BQ*REP, REP);
}

// round 5
// speedup vs baseline: 3.2899x; 1.0279x over previous
#include <cuda_runtime.h>
#include <cuda_bf16.h>
#include <math.h>
#include <stdint.h>

typedef unsigned short u16;

// ---------------- problem constants ----------------
#define BQ   512
#define CC   256
#define HH   7
#define WWD  7
#define HWX  49
#define M1   (BQ*HWX)      // 25088
#define SS   20
#define HWS  256
#define MS   (SS*HWS)      // 5120
#define REP  1024
#define FIN  (CC*HWX)      // 12544
#define CCAT 768
#define KX   (CC*9)        // 2304
#define KCAT (CCAT*9)      // 6912
#define NSPLIT 8

// ---------------- scratch (static device globals; no allocation) ----------------
__device__ u16 b_colx_h[(size_t)M1*KX],   b_colx_l[(size_t)M1*KX];
__device__ u16 b_colsup_h[(size_t)MS*KX], b_colsup_l[(size_t)MS*KX];
__device__ u16 b_colcat_h[(size_t)M1*KCAT], b_colcat_l[(size_t)M1*KCAT];
__device__ u16 b_wqv_h[CC*KX], b_wqv_l[CC*KX];
__device__ u16 b_wqk_h[CC*KX], b_wqk_l[CC*KX];
__device__ u16 b_wsv_h[CC*KX], b_wsv_l[CC*KX];
__device__ u16 b_wsk_h[CC*KX], b_wsk_l[CC*KX];
__device__ u16 b_wcat_h[CC*KCAT], b_wcat_l[CC*KCAT];
__device__ u16 b_w6c_h[(size_t)REP*FIN], b_w6c_l[(size_t)REP*FIN];
__device__ u16 b_w6r_h[(size_t)REP*FIN], b_w6r_l[(size_t)REP*FIN];
__device__ u16 b_w7c_h[REP*REP], b_w7c_l[REP*REP];
__device__ u16 b_w7r_h[REP*REP], b_w7r_l[REP*REP];
__device__ u16 b_qk_h[(size_t)M1*CC], b_qk_l[(size_t)M1*CC];
__device__ u16 b_sk_h[(size_t)MS*CC], b_sk_l[(size_t)MS*CC];
__device__ u16 b_svT_h[(size_t)CC*MS], b_svT_l[(size_t)CC*MS];
__device__ u16 b_Sh[(size_t)M1*MS], b_Sl[(size_t)M1*MS];
__device__ u16 b_fuse_h[(size_t)BQ*FIN], b_fuse_l[(size_t)BQ*FIN];
__device__ u16 b_hc_h[BQ*REP], b_hc_l[BQ*REP];
__device__ u16 b_hr_h[BQ*REP], b_hr_l[BQ*REP];
__device__ float g_qv[(size_t)M1*CC];
__device__ float g_qk[(size_t)M1*CC];
__device__ float g_sv[(size_t)MS*CC];
__device__ float g_attn[(size_t)M1*CC];
__device__ float g_attnchl[(size_t)M1*CC];
__device__ float g_fnhwc[(size_t)M1*CC];
__device__ float g_part[(size_t)NSPLIT*BQ*REP];
__device__ float g_gapin[SS*CC], g_gapval[SS*CC], g_gapkey[SS*CC];

// ---------------- helpers ----------------
__device__ __forceinline__ uint32_t smem_u32(const void* p) {
    uint32_t a;
    asm("{ .reg .u64 t; cvta.to.shared.u64 t, %1; cvt.u32.u64 %0, t; }" : "=r"(a) : "l"(p));
    return a;
}
#define SWZ(o) ((o) ^ (((o) >> 3) & 0x70))
__device__ __forceinline__ void ldsm_x4(uint32_t& r0, uint32_t& r1, uint32_t& r2, uint32_t& r3, uint32_t addr) {
    asm volatile("ldmatrix.sync.aligned.m8n8.x4.shared.b16 {%0,%1,%2,%3}, [%4];"
                 : "=r"(r0), "=r"(r1), "=r"(r2), "=r"(r3) : "r"(addr));
}
__device__ __forceinline__ void mma_bf16(float* c, const uint32_t* a, const uint32_t* b) {
    asm volatile("mma.sync.aligned.m16n8k16.row.col.f32.bf16.bf16.f32 "
                 "{%0,%1,%2,%3}, {%4,%5,%6,%7}, {%8,%9}, {%0,%1,%2,%3};"
                 : "+f"(c[0]), "+f"(c[1]), "+f"(c[2]), "+f"(c[3])
                 : "r"(a[0]), "r"(a[1]), "r"(a[2]), "r"(a[3]), "r"(b[0]), "r"(b[1]));
}
__device__ __forceinline__ void pack_hilo(float f0, float f1, uint32_t& hi, uint32_t& lo) {
    __nv_bfloat16 h0 = __float2bfloat16_rn(f0);
    __nv_bfloat16 h1 = __float2bfloat16_rn(f1);
    __nv_bfloat16 l0 = __float2bfloat16_rn(f0 - __bfloat162float(h0));
    __nv_bfloat16 l1 = __float2bfloat16_rn(f1 - __bfloat162float(h1));
    hi = (uint32_t)__bfloat16_as_ushort(h0) | ((uint32_t)__bfloat16_as_ushort(h1) << 16);
    lo = (uint32_t)__bfloat16_as_ushort(l0) | ((uint32_t)__bfloat16_as_ushort(l1) << 16);
}
__device__ __forceinline__ void hilo1(float f, u16& h, u16& l) {
    __nv_bfloat16 hb = __float2bfloat16_rn(f);
    __nv_bfloat16 lb = __float2bfloat16_rn(f - __bfloat162float(hb));
    h = __bfloat16_as_ushort(hb); l = __bfloat16_as_ushort(lb);
}
#define CPA(dst, src) asm volatile("cp.async.cg.shared.global [%0], [%1], 16;\n" :: "r"(dst), "l"(src))
#define CP_COMMIT()   asm volatile("cp.async.commit_group;\n" ::: "memory")
template<int NN> __device__ __forceinline__ void cp_wait() {
    asm volatile("cp.async.wait_group %0;\n" :: "n"(NN) : "memory");
}

// ================= bf16 hi/lo HMMA GEMM: C(M,N) = A(M,K) @ B(N,K)^T =================
// 128 thr (4 warps 2x2), CTA 128x128, warp tile 64x64, BK=32.
// cp.async double-buffered, swizzled smem, ldmatrix.x4 for both operands.
// OUTMODE: bit0 fp32 C, bit1 hi/lo bf16 C. Split-K via gridDim.z (fp32 partials).
#define TC_SMEM (65536 + 1024)
template<int OUTMODE, bool BIAS, bool RELU>
__global__ __launch_bounds__(128, 2)
void hgemm(const u16* __restrict__ Ah, const u16* __restrict__ Al,
           const u16* __restrict__ Bh, const u16* __restrict__ Bl,
           const float* __restrict__ bias,
           float* __restrict__ Cf, u16* __restrict__ Ch, u16* __restrict__ Cl,
           int M, int N, int K)
{
    extern __shared__ char dsm_raw[];
    const uint32_t raw = smem_u32(dsm_raw);
    const uint32_t sbase = (raw + 127u) & ~127u;
    uint32_t sb[2][4];
    #pragma unroll
    for (int b = 0; b < 2; b++)
        #pragma unroll
        for (int a = 0; a < 4; a++) sb[b][a] = sbase + (b*4 + a) * 8192;

    const int tid = threadIdx.x, wid = tid >> 5, lane = tid & 31;
    const int warp_m = wid & 1, warp_n = wid >> 1;
    const size_t m0 = (size_t)blockIdx.y * 128;
    const size_t n0 = (size_t)blockIdx.x * 128;
    const int kLen = K / gridDim.z;
    const int kbeg = blockIdx.z * kLen;
    const int nCh = kLen >> 5;

    // loader: per array 512 lines of 16B, 4 lines/thread
    int l_row[4]; uint32_t l_sw[4];
    #pragma unroll
    for (int r = 0; r < 4; r++) {
        const int line = tid + r * 128;
        l_row[r] = line >> 2;
        l_sw[r] = SWZ((uint32_t)(l_row[r]*64 + (line & 3)*16));
    }
    const int l_c8 = (tid & 3) * 8;   // element offset within row

    float acc[4][8][4];
    #pragma unroll
    for (int a = 0; a < 4; a++)
        #pragma unroll
        for (int b = 0; b < 8; b++)
            #pragma unroll
            for (int c = 0; c < 4; c++) acc[a][b][c] = 0.f;

    // fragment addresses (fixed per thread)
    const int a_row = warp_m * 64 + (lane & 15);
    const uint32_t a_kb = (uint32_t)(lane >> 4) * 16;           // k-half byte
    const int b_row = warp_n * 64 + ((lane >> 4) & 1) * 8 + (lane & 7);
    const uint32_t b_kb = (uint32_t)((lane >> 3) & 1) * 16;

    // prologue load
    {
        #pragma unroll
        for (int r = 0; r < 4; r++) {
            const size_t ga = (m0 + l_row[r]) * (size_t)K + kbeg + l_c8;
            const size_t gb = (n0 + l_row[r]) * (size_t)K + kbeg + l_c8;
            CPA(sb[0][0] + l_sw[r], Ah + ga);
            CPA(sb[0][1] + l_sw[r], Al + ga);
            CPA(sb[0][2] + l_sw[r], Bh + gb);
            CPA(sb[0][3] + l_sw[r], Bl + gb);
        }
        CP_COMMIT();
    }

    for (int ch = 0; ch < nCh; ++ch) {
        const int buf = ch & 1;
        if (ch + 1 < nCh) {
            const int k0 = kbeg + (ch + 1) * 32;
            const int nb = buf ^ 1;
            #pragma unroll
            for (int r = 0; r < 4; r++) {
                const size_t ga = (m0 + l_row[r]) * (size_t)K + k0 + l_c8;
                const size_t gb = (n0 + l_row[r]) * (size_t)K + k0 + l_c8;
                CPA(sb[nb][0] + l_sw[r], Ah + ga);
                CPA(sb[nb][1] + l_sw[r], Al + ga);
                CPA(sb[nb][2] + l_sw[r], Bh + gb);
                CPA(sb[nb][3] + l_sw[r], Bl + gb);
            }
            CP_COMMIT();
            cp_wait<1>();
        } else {
            cp_wait<0>();
        }
        __syncthreads();

        #pragma unroll
        for (int ks = 0; ks < 2; ks++) {
            const uint32_t kk2 = ks * 32;
            // B fragments: 8 n-tiles via 4 ldsm_x4 per array
            uint32_t bh[8][2], bl[8][2];
            #pragma unroll
            for (int ntp = 0; ntp < 4; ntp++) {
                const uint32_t off = SWZ((uint32_t)((b_row + ntp*16)*64) + kk2 + b_kb);
                ldsm_x4(bh[2*ntp][0], bh[2*ntp][1], bh[2*ntp+1][0], bh[2*ntp+1][1], sb[buf][2] + off);
                ldsm_x4(bl[2*ntp][0], bl[2*ntp][1], bl[2*ntp+1][0], bl[2*ntp+1][1], sb[buf][3] + off);
            }
            #pragma unroll
            for (int mt = 0; mt < 4; mt++) {
                const uint32_t off = SWZ((uint32_t)((a_row + mt*16)*64) + kk2 + a_kb);
                uint32_t ah[4], al[4];
                ldsm_x4(ah[0], ah[1], ah[2], ah[3], sb[buf][0] + off);
                ldsm_x4(al[0], al[1], al[2], al[3], sb[buf][1] + off);
                #pragma unroll
                for (int nt = 0; nt < 8; nt++) {
                    mma_bf16(acc[mt][nt], ah, bh[nt]);
                    mma_bf16(acc[mt][nt], ah, bl[nt]);
                    mma_bf16(acc[mt][nt], al, bh[nt]);
                }
            }
        }
        __syncthreads();
    }

    // epilogue
    float* Cfo = Cf + (size_t)blockIdx.z * (size_t)M * N;
    const int g = lane >> 2;
    const int cl2 = (lane & 3) * 2;
    #pragma unroll
    for (int mt = 0; mt < 4; mt++) {
        const size_t r0 = m0 + warp_m*64 + mt*16 + g;
        #pragma unroll
        for (int nt = 0; nt < 8; nt++) {
            const size_t cidx = n0 + warp_n*64 + nt*8 + cl2;
            float2 v0 = make_float2(acc[mt][nt][0], acc[mt][nt][1]);
            float2 v1 = make_float2(acc[mt][nt][2], acc[mt][nt][3]);
            if (BIAS) {
                const float b0 = bias[cidx], b1 = bias[cidx + 1];
                v0.x += b0; v0.y += b1; v1.x += b0; v1.y += b1;
            }
            if (RELU) {
                v0.x = fmaxf(v0.x, 0.f); v0.y = fmaxf(v0.y, 0.f);
                v1.x = fmaxf(v1.x, 0.f); v1.y = fmaxf(v1.y, 0.f);
            }
            if (OUTMODE & 1) {
                *(float2*)(Cfo + r0 * N + cidx) = v0;
                *(float2*)(Cfo + (r0 + 8) * N + cidx) = v1;
            }
            if (OUTMODE & 2) {
                uint32_t h0, l0, h1, l1;
                pack_hilo(v0.x, v0.y, h0, l0);
                pack_hilo(v1.x, v1.y, h1, l1);
                *(uint32_t*)&Ch[r0 * N + cidx] = h0;
                *(uint32_t*)&Cl[r0 * N + cidx] = l0;
                *(uint32_t*)&Ch[(r0 + 8) * N + cidx] = h1;
                *(uint32_t*)&Cl[(r0 + 8) * N + cidx] = l1;
            }
        }
    }
}

// ---------------- split-K reduce (+bias +relu) ----------------
template<bool HILO>
__global__ void reduce_splitk(const float* __restrict__ part, const float* __restrict__ bias,
                              float* __restrict__ outf, u16* __restrict__ oh, u16* __restrict__ ol,
                              int MN, int N)
{
    const int i = (blockIdx.x * 256 + threadIdx.x) * 4;
    if (i >= MN) return;
    float4 s = *(const float4*)(part + i);
    #pragma unroll
    for (int sp = 1; sp < NSPLIT; sp++) {
        float4 p = *(const float4*)(part + (size_t)sp * MN + i);
        s.x += p.x; s.y += p.y; s.z += p.z; s.w += p.w;
    }
    const int n = i & (N - 1);
    s.x = fmaxf(s.x + bias[n], 0.f);
    s.y = fmaxf(s.y + bias[n+1], 0.f);
    s.z = fmaxf(s.z + bias[n+2], 0.f);
    s.w = fmaxf(s.w + bias[n+3], 0.f);
    if (HILO) {
        uint32_t h0, l0, h1, l1;
        pack_hilo(s.x, s.y, h0, l0);
        pack_hilo(s.z, s.w, h1, l1);
        *(uint2*)&oh[i] = make_uint2(h0, h1);
        *(uint2*)&ol[i] = make_uint2(l0, l1);
    } else {
        *(float4*)(outf + i) = s;
    }
}

// ---------------- elementwise fp32 -> hi/lo ----------------
__global__ void cvt_hilo(const float* __restrict__ src, u16* __restrict__ h, u16* __restrict__ l, int n4)
{
    const int i = blockIdx.x * 256 + threadIdx.x;
    if (i >= n4) return;
    float4 v = ((const float4*)src)[i];
    uint32_t h0, l0, h1, l1;
    pack_hilo(v.x, v.y, h0, l0);
    pack_hilo(v.z, v.w, h1, l1);
    ((uint2*)h)[i] = make_uint2(h0, h1);
    ((uint2*)l)[i] = make_uint2(l0, l1);
}

// ---------------- fp32 (R,C) -> hi/lo (C,R) transpose+convert ----------------
__global__ void transpose_cvt(const float* __restrict__ src, u16* __restrict__ dh, u16* __restrict__ dl,
                              int R, int C)
{
    __shared__ float t[32][33];
    const int c0 = blockIdx.x * 32, r0 = blockIdx.y * 32;
    const int tx = threadIdx.x, ty = threadIdx.y;   // (32,8)
    for (int i = ty; i < 32; i += 8)
        t[i][tx] = src[(size_t)(r0 + i) * C + c0 + tx];
    __syncthreads();
    for (int i = ty; i < 32; i += 8) {
        u16 h, l; hilo1(t[tx][i], h, l);
        const size_t o = (size_t)(c0 + i) * R + r0 + tx;
        dh[o] = h; dl[o] = l;
    }
}

// ---------------- im2col (3x3 SAME) from NCHW fp32 -> hi/lo (M, Cin*9), 8 el/thread ----------------
__global__ void im2col_cvt(const float* __restrict__ X, u16* __restrict__ oh_, u16* __restrict__ ol_,
                           int Mr, int Cin, int HW, int Hd, int Wd)
{
    const int K = Cin * 9;
    const int Kq = K >> 3;
    const uint32_t idx = blockIdx.x * 256 + threadIdx.x;
    if (idx >= (uint32_t)Mr * Kq) return;
    const int m = idx / Kq;
    const int k0 = (idx - m * Kq) * 8;
    const int b = m / HW, p = m - b * HW;
    const int oh = p / Wd, ow = p - oh * Wd;
    const float* xb = X + (size_t)b * Cin * HW;
    u16 hs[8], ls[8];
    #pragma unroll
    for (int j = 0; j < 8; j++) {
        const int k = k0 + j;
        const int ci = k / 9, t = k - ci * 9;
        const int dh = t / 3, dw = t - dh * 3;
        const int ih = oh + dh - 1, iw = ow + dw - 1;
        float v = (ih >= 0 && ih < Hd && iw >= 0 && iw < Wd) ? xb[(size_t)ci * HW + ih * Wd + iw] : 0.f;
        hilo1(v, hs[j], ls[j]);
    }
    const size_t o = (size_t)m * K + k0;
    *(uint4*)&oh_[o] = make_uint4((uint32_t)hs[0]|((uint32_t)hs[1]<<16), (uint32_t)hs[2]|((uint32_t)hs[3]<<16),
                                  (uint32_t)hs[4]|((uint32_t)hs[5]<<16), (uint32_t)hs[6]|((uint32_t)hs[7]<<16));
    *(uint4*)&ol_[o] = make_uint4((uint32_t)ls[0]|((uint32_t)ls[1]<<16), (uint32_t)ls[2]|((uint32_t)ls[3]<<16),
                                  (uint32_t)ls[4]|((uint32_t)ls[5]<<16), (uint32_t)ls[6]|((uint32_t)ls[7]<<16));
}

// ---------------- im2col of the 768-ch concat, direct from 3 NHWC sources, 8 el/thread ----------------
__global__ void im2col_cat_cvt(const float* __restrict__ s0, const float* __restrict__ s1,
                               const float* __restrict__ s2,
                               u16* __restrict__ oh_, u16* __restrict__ ol_)
{
    const int K = KCAT;
    const int Kq = K >> 3;
    const uint32_t idx = blockIdx.x * 256 + threadIdx.x;
    if (idx >= (uint32_t)M1 * Kq) return;
    const int m = idx / Kq;
    const int k0 = (idx - m * Kq) * 8;
    const int b = m / HWX, p = m - b * HWX;
    const int oh = p / WWD, ow = p - oh * WWD;
    u16 hs[8], ls[8];
    #pragma unroll
    for (int j = 0; j < 8; j++) {
        const int k = k0 + j;
        const int c = k / 9, t = k - c * 9;
        const int dh = t / 3, dw = t - dh * 3;
        const int ih = oh + dh - 1, iw = ow + dw - 1;
        float v = 0.f;
        if (ih >= 0 && ih < HH && iw >= 0 && iw < WWD) {
            const float* src = (c < 256) ? s0 : ((c < 512) ? s1 : s2);
            v = src[((size_t)(b * HWX + ih * WWD + iw)) * 256 + (c & 255)];
        }
        hilo1(v, hs[j], ls[j]);
    }
    const size_t o = (size_t)m * K + k0;
    *(uint4*)&oh_[o] = make_uint4((uint32_t)hs[0]|((uint32_t)hs[1]<<16), (uint32_t)hs[2]|((uint32_t)hs[3]<<16),
                                  (uint32_t)hs[4]|((uint32_t)hs[5]<<16), (uint32_t)hs[6]|((uint32_t)hs[7]<<16));
    *(uint4*)&ol_[o] = make_uint4((uint32_t)ls[0]|((uint32_t)ls[1]<<16), (uint32_t)ls[2]|((uint32_t)ls[3]<<16),
                                  (uint32_t)ls[4]|((uint32_t)ls[5]<<16), (uint32_t)ls[6]|((uint32_t)ls[7]<<16));
}

// ---------------- NHWC fp32 -> NCHW-flat hi/lo (fuse) ----------------
__global__ void pack_fuse(const float* __restrict__ src, u16* __restrict__ fh, u16* __restrict__ fl)
{
    __shared__ float tile[49][33];
    const int b = blockIdx.x, cg = blockIdx.y;
    const int tx = threadIdx.x, ty = threadIdx.y;   // (32,8)
    for (int p = ty; p < 49; p += 8)
        tile[p][tx] = src[((size_t)b*49 + p)*256 + cg*32 + tx];
    __syncthreads();
    for (int cc = ty; cc < 32; cc += 8) {
        const size_t base = (size_t)b * FIN + (cg*32 + cc) * 49;
        u16 h, l;
        hilo1(tile[tx][cc], h, l);
        fh[base + tx] = h; fl[base + tx] = l;
        if (tx + 32 < 49) {
            hilo1(tile[tx + 32][cc], h, l);
            fh[base + tx + 32] = h; fl[base + tx + 32] = l;
        }
    }
}

// ---------------- sup spatial mean ----------------
__global__ void gap_mean_kernel(const float* __restrict__ sup, float* __restrict__ out)
{
    const int gw = (blockIdx.x * blockDim.x + threadIdx.x) >> 5;
    const int lane = threadIdx.x & 31;
    if (gw >= SS*CC) return;
    const float* pch = sup + (size_t)gw * HWS;
    float s = 0.f;
    for (int i = lane; i < HWS; i += 32) s += pch[i];
    #pragma unroll
    for (int o = 16; o; o >>= 1) s += __shfl_xor_sync(0xffffffffu, s, o);
    if (lane == 0) out[gw] = s * (1.f / 256.f);
}

// ---------------- gap "convs" (center tap; key/value names swapped per reference) ----------------
__global__ __launch_bounds__(256)
void gap_fc_kernel(const float* __restrict__ gapin,
                   const float* __restrict__ gkw, const float* __restrict__ gkb,
                   const float* __restrict__ gvw, const float* __restrict__ gvb,
                   float* __restrict__ gapval, float* __restrict__ gapkey)
{
    const int s = blockIdx.x;
    const int co = threadIdx.x;
    __shared__ float gin[CC];
    gin[co] = gapin[s*CC + co];
    __syncthreads();
    float a = gkb[co], b = gvb[co];
    for (int ci = 0; ci < CC; ci++) {
        const float g = gin[ci];
        a += g * gkw[(size_t)(co*CC + ci)*9 + 4];
        b += g * gvw[(size_t)(co*CC + ci)*9 + 4];
    }
    gapval[s*CC + co] = a;
    gapkey[s*CC + co] = b;
}

// ---------------- row softmax over hi/lo S (N=5120), in-place hi/lo P out ----------------
__global__ __launch_bounds__(256)
void softmax_hilo(u16* __restrict__ Sh, u16* __restrict__ Sl)
{
    __shared__ float row[MS];
    __shared__ float sm[32];
    __shared__ float bcast;
    const int m = blockIdx.x;
    const int tid = threadIdx.x, lane = tid & 31, w = tid >> 5;
    u16* ph = Sh + (size_t)m * MS;
    u16* pl = Sl + (size_t)m * MS;

    float mx = -1e30f;
    for (int i = tid*4; i < MS; i += 1024) {
        uint2 hh = *(const uint2*)&ph[i];
        uint2 ll = *(const uint2*)&pl[i];
        float4 v;
        v.x = __bfloat162float(__ushort_as_bfloat16((u16)(hh.x & 0xffff))) + __bfloat162float(__ushort_as_bfloat16((u16)(ll.x & 0xffff)));
        v.y = __bfloat162float(__ushort_as_bfloat16((u16)(hh.x >> 16)))    + __bfloat162float(__ushort_as_bfloat16((u16)(ll.x >> 16)));
        v.z = __bfloat162float(__ushort_as_bfloat16((u16)(hh.y & 0xffff))) + __bfloat162float(__ushort_as_bfloat16((u16)(ll.y & 0xffff)));
        v.w = __bfloat162float(__ushort_as_bfloat16((u16)(hh.y >> 16)))    + __bfloat162float(__ushort_as_bfloat16((u16)(ll.y >> 16)));
        *(float4*)&row[i] = v;
        mx = fmaxf(fmaxf(fmaxf(mx, v.x), fmaxf(v.y, v.z)), v.w);
    }
    #pragma unroll
    for (int o = 16; o; o >>= 1) mx = fmaxf(mx, __shfl_xor_sync(0xffffffffu, mx, o));
    if (lane == 0) sm[w] = mx;
    __syncthreads();
    if (tid < 32) {
        float v = (tid < 8) ? sm[tid] : -1e30f;
        #pragma unroll
        for (int o = 16; o; o >>= 1) v = fmaxf(v, __shfl_xor_sync(0xffffffffu, v, o));
        if (tid == 0) bcast = v;
    }
    __syncthreads();
    mx = bcast;
    __syncthreads();

    float sum = 0.f;
    for (int i = tid*4; i < MS; i += 1024) {
        float4 v = *(float4*)&row[i];
        v.x = __expf(v.x - mx); v.y = __expf(v.y - mx);
        v.z = __expf(v.z - mx); v.w = __expf(v.w - mx);
        *(float4*)&row[i] = v;
        sum += v.x + v.y + v.z + v.w;
    }
    #pragma unroll
    for (int o = 16; o; o >>= 1) sum += __shfl_xor_sync(0xffffffffu, sum, o);
    if (lane == 0) sm[w] = sum;
    __syncthreads();
    if (tid < 32) {
        float v = (tid < 8) ? sm[tid] : 0.f;
        #pragma unroll
        for (int o = 16; o; o >>= 1) v += __shfl_xor_sync(0xffffffffu, v, o);
        if (tid == 0) bcast = v;
    }
    __syncthreads();
    const float inv = 1.f / bcast;
    for (int i = tid*4; i < MS; i += 1024) {
        float4 v = *(float4*)&row[i];
        uint32_t h0, l0, h1, l1;
        pack_hilo(v.x * inv, v.y * inv, h0, l0);
        pack_hilo(v.z * inv, v.w * inv, h1, l1);
        *(uint2*)&ph[i] = make_uint2(h0, h1);
        *(uint2*)&pl[i] = make_uint2(l0, l1);
    }
}

// ---------------- fused channel attention ----------------
__global__ __launch_bounds__(256)
void chl_attn_kernel(const float* __restrict__ qk, const float* __restrict__ gapkey,
                     const float* __restrict__ gapval, float* __restrict__ out)
{
    const int m = blockIdx.x;
    __shared__ float qrow[CC];
    __shared__ float pr[SS];
    const int tid = threadIdx.x;
    qrow[tid] = qk[(size_t)m*CC + tid];
    __syncthreads();
    if (tid < SS) {
        const float* krow = gapkey + tid*CC;
        float acc = 0.f;
        #pragma unroll 8
        for (int i = 0; i < CC; i++) acc += qrow[i] * krow[i];
        pr[tid] = acc;
    }
    __syncthreads();
    if (tid == 0) {
        float mx = -1e30f;
        #pragma unroll
        for (int s = 0; s < SS; s++) mx = fmaxf(mx, pr[s]);
        float sum = 0.f;
        #pragma unroll
        for (int s = 0; s < SS; s++) { float e = __expf(pr[s] - mx); pr[s] = e; sum += e; }
        const float inv = 1.f / sum;
        #pragma unroll
        for (int s = 0; s < SS; s++) pr[s] *= inv;
    }
    __syncthreads();
    float acc = 0.f;
    #pragma unroll
    for (int s = 0; s < SS; s++) acc += pr[s] * gapval[s*CC + tid];
    out[(size_t)m*CC + tid] = acc;
}

// ---------------- launch ----------------
extern "C" void kernel_launch(void* const* d_in, const int* in_sizes, int n_in,
                              void* d_out, int out_size)
{
    const float* x     = (const float*)d_in[0];
    const float* sup   = (const float*)d_in[1];
    const float* qv_w  = (const float*)d_in[2];
    const float* qv_b  = (const float*)d_in[3];
    const float* qk_w  = (const float*)d_in[4];
    const float* qk_b  = (const float*)d_in[5];
    const float* gk_w  = (const float*)d_in[6];
    const float* gk_b  = (const float*)d_in[7];
    const float* gv_w  = (const float*)d_in[8];
    const float* gv_b  = (const float*)d_in[9];
    const float* sv_w  = (const float*)d_in[10];
    const float* sv_b  = (const float*)d_in[11];
    const float* sk_w  = (const float*)d_in[12];
    const float* sk_b  = (const float*)d_in[13];
    const float* cat_w = (const float*)d_in[14];
    const float* cat_b = (const float*)d_in[15];
    const float* fc6c_w = (const float*)d_in[16];
    const float* fc6c_b = (const float*)d_in[17];
    const float* fc7c_w = (const float*)d_in[18];
    const float* fc7c_b = (const float*)d_in[19];
    const float* fc6r_w = (const float*)d_in[20];
    const float* fc6r_b = (const float*)d_in[21];
    const float* fc7r_w = (const float*)d_in[22];
    const float* fc7r_b = (const float*)d_in[23];
    float* out = (float*)d_out;

    u16 *colx_h,*colx_l,*colsup_h,*colsup_l,*colcat_h,*colcat_l;
    u16 *wqv_h,*wqv_l,*wqk_h,*wqk_l,*wsv_h,*wsv_l,*wsk_h,*wsk_l,*wcat_h,*wcat_l;
    u16 *w6c_h,*w6c_l,*w6r_h,*w6r_l,*w7c_h,*w7c_l,*w7r_h,*w7r_l;
    u16 *qk_h,*qk_l,*sk_h,*sk_l,*svT_h,*svT_l,*Sh,*Sl,*fuse_h,*fuse_l,*hc_h,*hc_l,*hr_h,*hr_l;
    float *p_qv,*p_qk,*p_sv,*p_attn,*p_attnchl,*p_fnhwc,*p_part,*p_gapin,*p_gapval,*p_gapkey;
    #define SYM(v, s) cudaGetSymbolAddress((void**)&v, s)
    SYM(colx_h,b_colx_h); SYM(colx_l,b_colx_l); SYM(colsup_h,b_colsup_h); SYM(colsup_l,b_colsup_l);
    SYM(colcat_h,b_colcat_h); SYM(colcat_l,b_colcat_l);
    SYM(wqv_h,b_wqv_h); SYM(wqv_l,b_wqv_l); SYM(wqk_h,b_wqk_h); SYM(wqk_l,b_wqk_l);
    SYM(wsv_h,b_wsv_h); SYM(wsv_l,b_wsv_l); SYM(wsk_h,b_wsk_h); SYM(wsk_l,b_wsk_l);
    SYM(wcat_h,b_wcat_h); SYM(wcat_l,b_wcat_l);
    SYM(w6c_h,b_w6c_h); SYM(w6c_l,b_w6c_l); SYM(w6r_h,b_w6r_h); SYM(w6r_l,b_w6r_l);
    SYM(w7c_h,b_w7c_h); SYM(w7c_l,b_w7c_l); SYM(w7r_h,b_w7r_h); SYM(w7r_l,b_w7r_l);
    SYM(qk_h,b_qk_h); SYM(qk_l,b_qk_l); SYM(sk_h,b_sk_h); SYM(sk_l,b_sk_l);
    SYM(svT_h,b_svT_h); SYM(svT_l,b_svT_l); SYM(Sh,b_Sh); SYM(Sl,b_Sl);
    SYM(fuse_h,b_fuse_h); SYM(fuse_l,b_fuse_l);
    SYM(hc_h,b_hc_h); SYM(hc_l,b_hc_l); SYM(hr_h,b_hr_h); SYM(hr_l,b_hr_l);
    SYM(p_qv,g_qv); SYM(p_qk,g_qk); SYM(p_sv,g_sv);
    SYM(p_attn,g_attn); SYM(p_attnchl,g_attnchl); SYM(p_fnhwc,g_fnhwc); SYM(p_part,g_part);
    SYM(p_gapin,g_gapin); SYM(p_gapval,g_gapval); SYM(p_gapkey,g_gapkey);

    cudaFuncSetAttribute(hgemm<1,true,false>, cudaFuncAttributeMaxDynamicSharedMemorySize, TC_SMEM);
    cudaFuncSetAttribute(hgemm<3,true,false>, cudaFuncAttributeMaxDynamicSharedMemorySize, TC_SMEM);
    cudaFuncSetAttribute(hgemm<2,true,false>, cudaFuncAttributeMaxDynamicSharedMemorySize, TC_SMEM);
    cudaFuncSetAttribute(hgemm<2,false,false>, cudaFuncAttributeMaxDynamicSharedMemorySize, TC_SMEM);
    cudaFuncSetAttribute(hgemm<1,false,false>, cudaFuncAttributeMaxDynamicSharedMemorySize, TC_SMEM);
    cudaFuncSetAttribute(hgemm<1,true,true>, cudaFuncAttributeMaxDynamicSharedMemorySize, TC_SMEM);

    // gap path
    gap_mean_kernel<<<(SS*CC*32 + 255)/256, 256>>>(sup, p_gapin);
    gap_fc_kernel<<<SS, 256>>>(p_gapin, gk_w, gk_b, gv_w, gv_b, p_gapval, p_gapkey);
    // im2col of x and sup
    im2col_cvt<<<(int)(((size_t)M1*KX/8 + 255)/256), 256>>>(x, colx_h, colx_l, M1, CC, HWX, HH, WWD);
    im2col_cvt<<<(int)(((size_t)MS*KX/8 + 255)/256), 256>>>(sup, colsup_h, colsup_l, MS, CC, HWS, 16, 16);
    // qv conv
    cvt_hilo<<<(CC*KX/4 + 255)/256, 256>>>(qv_w, wqv_h, wqv_l, CC*KX/4);
    hgemm<1,true,false><<<dim3(CC/128, M1/128), 128, TC_SMEM>>>(colx_h, colx_l, wqv_h, wqv_l, qv_b, p_qv, nullptr, nullptr, M1, CC, KX);
    // qk conv (fp32 + hilo)
    cvt_hilo<<<(CC*KX/4 + 255)/256, 256>>>(qk_w, wqk_h, wqk_l, CC*KX/4);
    hgemm<3,true,false><<<dim3(CC/128, M1/128), 128, TC_SMEM>>>(colx_h, colx_l, wqk_h, wqk_l, qk_b, p_qk, qk_h, qk_l, M1, CC, KX);
    // sv conv (fp32)
    cvt_hilo<<<(CC*KX/4 + 255)/256, 256>>>(sv_w, wsv_h, wsv_l, CC*KX/4);
    hgemm<1,true,false><<<dim3(CC/128, MS/128), 128, TC_SMEM>>>(colsup_h, colsup_l, wsv_h, wsv_l, sv_b, p_sv, nullptr, nullptr, MS, CC, KX);
    // sk conv (hilo only)
    cvt_hilo<<<(CC*KX/4 + 255)/256, 256>>>(sk_w, wsk_h, wsk_l, CC*KX/4);
    hgemm<2,true,false><<<dim3(CC/128, MS/128), 128, TC_SMEM>>>(colsup_h, colsup_l, wsk_h, wsk_l, sk_b, nullptr, sk_h, sk_l, MS, CC, KX);
    // svT
    transpose_cvt<<<dim3(CC/32, MS/32), dim3(32,8)>>>(p_sv, svT_h, svT_l, MS, CC);
    // QK^T -> S hi/lo directly
    hgemm<2,false,false><<<dim3(MS/128, M1/128), 128, TC_SMEM>>>(qk_h, qk_l, sk_h, sk_l, nullptr, nullptr, Sh, Sl, M1, MS, CC);
    // softmax in place on hi/lo
    softmax_hilo<<<M1, 256>>>(Sh, Sl);
    // channel attention
    chl_attn_kernel<<<M1, 256>>>(p_qk, p_gapkey, p_gapval, p_attnchl);
    // attn = P @ V
    hgemm<1,false,false><<<dim3(CC/128, M1/128), 128, TC_SMEM>>>(Sh, Sl, svT_h, svT_l, nullptr, p_attn, nullptr, nullptr, M1, CC, MS);
    // im2col of concat
    im2col_cat_cvt<<<(int)(((size_t)M1*KCAT/8 + 255)/256), 256>>>(p_qv, p_attn, p_attnchl, colcat_h, colcat_l);
    // cat conv + ReLU
    cvt_hilo<<<(CC*KCAT/4 + 255)/256, 256>>>(cat_w, wcat_h, wcat_l, CC*KCAT/4);
    hgemm<1,true,true><<<dim3(CC/128, M1/128), 128, TC_SMEM>>>(colcat_h, colcat_l, wcat_h, wcat_l, cat_b, p_fnhwc, nullptr, nullptr, M1, CC, KCAT);
    // pack fuse
    pack_fuse<<<dim3(BQ, CC/32), dim3(32,8)>>>(p_fnhwc, fuse_h, fuse_l);
    // FC heads, split-K=8
    transpose_cvt<<<dim3(REP/32, FIN/32), dim3(32,8)>>>(fc6c_w, w6c_h, w6c_l, FIN, REP);
    hgemm<1,false,false><<<dim3(REP/128, BQ/128, NSPLIT), 128, TC_SMEM>>>(fuse_h, fuse_l, w6c_h, w6c_l, nullptr, p_part, nullptr, nullptr, BQ, REP, FIN);
    reduce_splitk<true><<<(BQ*REP/4 + 255)/256, 256>>>(p_part, fc6c_b, nullptr, hc_h, hc_l, BQ*REP, REP);
    transpose_cvt<<<dim3(REP/32, REP/32), dim3(32,8)>>>(fc7c_w, w7c_h, w7c_l, REP, REP);
    hgemm<1,false,false><<<dim3(REP/128, BQ/128, NSPLIT), 128, TC_SMEM>>>(hc_h, hc_l, w7c_h, w7c_l, nullptr, p_part, nullptr, nullptr, BQ, REP, REP);
    reduce_splitk<false><<<(BQ*REP/4 + 255)/256, 256>>>(p_part, fc7c_b, out, nullptr, nullptr, BQ*REP, REP);
    transpose_cvt<<<dim3(REP/32, FIN/32), dim3(32,8)>>>(fc6r_w, w6r_h, w6r_l, FIN, REP);
    hgemm<1,false,false><<<dim3(REP/128, BQ/128, NSPLIT), 128, TC_SMEM>>>(fuse_h, fuse_l, w6r_h, w6r_l, nullptr, p_part, nullptr, nullptr, BQ, REP, FIN);
    reduce_splitk<true><<<(BQ*REP/4 + 255)/256, 256>>>(p_part, fc6r_b, nullptr, hr_h, hr_l, BQ*REP, REP);
    transpose_cvt<<<dim3(REP/32, REP/32), dim3(32,8)>>>(fc7r_w, w7r_h, w7r_l, REP, REP);
    hgemm<1,false,false><<<dim3(REP/128, BQ/128, NSPLIT), 128, TC_SMEM>>>(hr_h, hr_l, w7r_h, w7r_l, nullptr, p_part, nullptr, nullptr, BQ, REP, REP);
    reduce_splitk<false><<<(BQ*REP/4 + 255)/256, 256>>>(p_part, fc7r_b, out + (size_t)BQ*REP, nullptr, nullptr, BQ*REP, REP);
}